// round 15
// baseline (speedup 1.0000x reference)
#include <cuda_runtime.h>
#include <cuda_fp16.h>
#include <math.h>
#include <stdint.h>

// ---------------- problem constants ----------------
#define BB    128
#define NI    8192
#define NW    16384
#define EE    64
#define KP    4
#define TWOE  128

#define OUT_RATING  0
#define OUT_TEXT    (128*8192)
#define OUT_CFMU    (OUT_TEXT + 128*16384)
#define OUT_CFLV    (OUT_CFMU + 4*128*64)
#define OUT_TXMU    (OUT_CFLV + 4*128*64)
#define OUT_TXLV    (OUT_TXMU + 4*128*64)

#define HSPLIT 32
#define ASPLIT 4

// fp16 mma tile config (128x128), BLKK=32 path (P1 / hpart)
#define BLKK   32
#define LDH    40
#define BUFH   (128*LDH)
#define BUF_BYTES (BUFH*2)                 // 10240
#define SMEM_GEMM (4*BUF_BYTES)            // 40960

// BLKK=64 path (P2, pure cp.async)
#define BLKK2  64
#define LDH2   72                          // 144B stride, LDSM conflict-free
#define BUFH2  (128*LDH2)
#define BUF2_BYTES (BUFH2*2)               // 18432
#define SMEM_A16 (4*BUF2_BYTES)            // 2A + 2B = 73728

// ---------------- scratch ----------------
__device__ float g_protos_cf[KP*EE];
__device__ float g_protos_tx[KP*EE];
__device__ float g_items_cf[NI*EE];
__device__ float g_items_tx[NW*EE];
__device__ float g_cates_cf[NI*KP];
__device__ float g_cates_tx[NW*KP];
__device__ float g_ctT_cf[KP*NI];
__device__ float g_ctT_tx[KP*NW];
__device__ float g_rnp_cf[KP*BB*8];
__device__ float g_rnp_tx[KP*BB*8];
__device__ __half g_adj16[(size_t)NI*NI];
__device__ __half g_W16cf[TWOE*NI];
__device__ __half g_W16tx[TWOE*NW];
__device__ __half g_P1T16[TWOE*NI];
__device__ __half g_MT16 [TWOE*NI];
__device__ float g_bigpart[ASPLIT*NI*TWOE];
__device__ float g_part_cf[HSPLIT*512*TWOE];
__device__ float g_part_tx[HSPLIT*512*TWOE];

// ---------------- helpers ----------------
__device__ __forceinline__ void mma_f16(float c[4], const uint32_t a[4],
                                        uint32_t b0, uint32_t b1) {
    asm volatile(
        "mma.sync.aligned.m16n8k16.row.col.f32.f16.f16.f32 "
        "{%0,%1,%2,%3}, {%4,%5,%6,%7}, {%8,%9}, {%0,%1,%2,%3};"
        : "+f"(c[0]), "+f"(c[1]), "+f"(c[2]), "+f"(c[3])
        : "r"(a[0]), "r"(a[1]), "r"(a[2]), "r"(a[3]), "r"(b0), "r"(b1));
}
__device__ __forceinline__ void ldsm4(uint32_t& r0, uint32_t& r1,
                                      uint32_t& r2, uint32_t& r3, uint32_t addr) {
    asm volatile("ldmatrix.sync.aligned.m8n8.x4.shared.b16 {%0,%1,%2,%3}, [%4];"
                 : "=r"(r0), "=r"(r1), "=r"(r2), "=r"(r3) : "r"(addr));
}
__device__ __forceinline__ uint32_t pack_h2(float a, float b) {
    __half2 h = __floats2half2_rn(a, b);
    return *reinterpret_cast<uint32_t*>(&h);
}
#define CP16(dst, src) \
    asm volatile("cp.async.cg.shared.global [%0], [%1], 16;" :: "r"(dst), "l"(src) : "memory")
#define CP_COMMIT() asm volatile("cp.async.commit_group;" ::: "memory")
#define CP_WAIT0()  asm volatile("cp.async.wait_group 0;" ::: "memory")
#define CP_WAIT1()  asm volatile("cp.async.wait_group 1;" ::: "memory")

// FMA-pipe exp for |x| <= ~1.05 (degree-9 Taylor, rel err ~3e-7)
__device__ __forceinline__ float exp_t9(float x) {
    float r = 2.7557319e-6f;
    r = fmaf(r, x, 2.4801587e-5f);
    r = fmaf(r, x, 1.9841270e-4f);
    r = fmaf(r, x, 1.3888889e-3f);
    r = fmaf(r, x, 8.3333333e-3f);
    r = fmaf(r, x, 4.1666667e-2f);
    r = fmaf(r, x, 1.6666667e-1f);
    r = fmaf(r, x, 0.5f);
    r = fmaf(r, x, 1.0f);
    r = fmaf(r, x, 1.0f);
    return r;
}
// FMA-pipe log (exponent extract + deg-14 log1p, rel err ~1e-7)
__device__ __forceinline__ float log_poly(float p) {
    int ib = __float_as_int(p);
    int e = ((ib >> 23) & 255) - 127;
    float m = __int_as_float((ib & 0x007fffff) | 0x3f800000);
    if (m > 1.4142135f) { m *= 0.5f; e += 1; }
    float u = m - 1.0f;
    float r = -1.0f/14.0f;
    r = fmaf(r, u,  1.0f/13.0f);
    r = fmaf(r, u, -1.0f/12.0f);
    r = fmaf(r, u,  1.0f/11.0f);
    r = fmaf(r, u, -0.1f);
    r = fmaf(r, u,  1.0f/9.0f);
    r = fmaf(r, u, -0.125f);
    r = fmaf(r, u,  1.0f/7.0f);
    r = fmaf(r, u, -1.0f/6.0f);
    r = fmaf(r, u,  0.2f);
    r = fmaf(r, u, -0.25f);
    r = fmaf(r, u,  1.0f/3.0f);
    r = fmaf(r, u, -0.5f);
    r = fmaf(r, u,  1.0f);
    r = r * u;
    return fmaf((float)e, 0.69314718f, r);
}

// ---------------- k0: normalize prototypes ----------------
__global__ void proto_norm_k(const float* __restrict__ cfp, const float* __restrict__ txp) {
    int tid = threadIdx.x;
    int w = tid >> 5, lane = tid & 31;
    const float* src = (w < 4) ? cfp : txp;
    float* dst = (w < 4) ? g_protos_cf : g_protos_tx;
    int row = w & 3;
    float v0 = src[row*EE + lane];
    float v1 = src[row*EE + 32 + lane];
    float s = v0*v0 + v1*v1;
    #pragma unroll
    for (int off = 16; off; off >>= 1) s += __shfl_xor_sync(0xffffffffu, s, off);
    float inv = 1.0f / fmaxf(sqrtf(s), 1e-12f);
    dst[row*EE + lane]      = v0 * inv;
    dst[row*EE + 32 + lane] = v1 * inv;
}

// ---------------- convert W rows to scaled fp16 ----------------
__global__ void __launch_bounds__(256) convW_k(const float4* __restrict__ in,
                                              uint2* __restrict__ out, float scale) {
    int i = blockIdx.x * 256 + threadIdx.x;
    float4 v = in[i];
    uint2 u;
    u.x = pack_h2(v.x*scale, v.y*scale);
    u.y = pack_h2(v.z*scale, v.w*scale);
    out[i] = u;
}

// ---------------- k1: item norm + cates softmax (+ transposed) ----------------
__global__ void __launch_bounds__(256) items_cates_k(
        const float* __restrict__ emb, const float* __restrict__ protos_g,
        float* __restrict__ items_out, float* __restrict__ cates_out,
        float* __restrict__ catesT_out, int N)
{
    __shared__ float ps[KP*EE];
    int tid = threadIdx.x;
    ps[tid] = protos_g[tid];
    __syncthreads();
    int w = tid >> 5, lane = tid & 31;
    int n = blockIdx.x * 8 + w;
    if (n >= N) return;
    float v0 = emb[n*EE + lane];
    float v1 = emb[n*EE + 32 + lane];
    float s = v0*v0 + v1*v1;
    #pragma unroll
    for (int off = 16; off; off >>= 1) s += __shfl_xor_sync(0xffffffffu, s, off);
    float inv = 1.0f / fmaxf(sqrtf(s), 1e-12f);
    float h0 = v0 * inv, h1 = v1 * inv;
    items_out[n*EE + lane]      = h0;
    items_out[n*EE + 32 + lane] = h1;
    float d[KP];
    #pragma unroll
    for (int k = 0; k < KP; k++) {
        float dk = h0 * ps[k*EE + lane] + h1 * ps[k*EE + 32 + lane];
        #pragma unroll
        for (int off = 16; off; off >>= 1) dk += __shfl_xor_sync(0xffffffffu, dk, off);
        d[k] = dk;
    }
    if (lane == 0) {
        float m = fmaxf(fmaxf(d[0], d[1]), fmaxf(d[2], d[3]));
        float e0 = __expf(d[0]-m), e1 = __expf(d[1]-m), e2 = __expf(d[2]-m), e3 = __expf(d[3]-m);
        float is = 1.0f / (e0+e1+e2+e3);
        float c0 = e0*is, c1 = e1*is, c2 = e2*is, c3 = e3*is;
        *(float4*)&cates_out[n*KP] = make_float4(c0, c1, c2, c3);
        catesT_out[0*N + n] = c0;
        catesT_out[1*N + n] = c1;
        catesT_out[2*N + n] = c2;
        catesT_out[3*N + n] = c3;
    }
}

// ---------------- k2: rnorm partials ----------------
__global__ void __launch_bounds__(256) rnormp_k(
        const float* __restrict__ x, const float* __restrict__ cates,
        float* __restrict__ rnp, int N)
{
    __shared__ float red[8][KP];
    int b = blockIdx.x, chunk = blockIdx.y, tid = threadIdx.x;
    int n0 = chunk * (N >> 3), n1 = n0 + (N >> 3);
    float s0=0.f, s1=0.f, s2=0.f, s3=0.f;
    const float* xr = x + (size_t)b * N;
    for (int n = n0 + tid; n < n1; n += 256) {
        float xv = xr[n];
        float4 c = *(const float4*)&cates[n*KP];
        float t0 = xv*c.x, t1 = xv*c.y, t2 = xv*c.z, t3 = xv*c.w;
        s0 += t0*t0; s1 += t1*t1; s2 += t2*t2; s3 += t3*t3;
    }
    #pragma unroll
    for (int off = 16; off; off >>= 1) {
        s0 += __shfl_xor_sync(0xffffffffu, s0, off);
        s1 += __shfl_xor_sync(0xffffffffu, s1, off);
        s2 += __shfl_xor_sync(0xffffffffu, s2, off);
        s3 += __shfl_xor_sync(0xffffffffu, s3, off);
    }
    int w = tid >> 5;
    if ((tid & 31) == 0) { red[w][0]=s0; red[w][1]=s1; red[w][2]=s2; red[w][3]=s3; }
    __syncthreads();
    if (tid < KP) {
        float t = 0.f;
        #pragma unroll
        for (int i = 0; i < 8; i++) t += red[i][tid];
        rnp[(tid*BB + b)*8 + chunk] = t;
    }
}

// ---------------- FP16 MMA GEMM (templated A-mode), B fp16 via cp.async --------
template<int AMODE>
__global__ void __launch_bounds__(256) mma_gemm_t(
        const float* __restrict__ A, const float* __restrict__ ctT,
        const __half* __restrict__ B16,
        float* __restrict__ part, __half* __restrict__ aout,
        int Mrows, int Ktot, int Ksplit, float ascale, float inv_ab)
{
    extern __shared__ __half hsm[];
    __half* Asm = hsm;
    int tid = threadIdx.x;
    int lane = tid & 31, w = tid >> 5;
    int wm = w & 3, wn = w >> 2;
    int lr = lane >> 2, lc = lane & 3;
    int m0 = blockIdx.x * 128;
    int kc0 = blockIdx.z * Ksplit;
    int niter = Ksplit / BLKK;
    const float* ctb = (AMODE == 1) ? (ctT + (size_t)blockIdx.x * Ktot) : (const float*)0;

    uint32_t as_base = (uint32_t)__cvta_generic_to_shared(Asm);
    uint32_t bs_base = as_base + 2*BUF_BYTES;
    int sel = lane >> 3, lr8 = lane & 7;
    uint32_t a_off = (uint32_t)(((wm*32 + (sel&1)*8 + lr8)*LDH + (sel>>1)*8) * 2);
    uint32_t b_off = (uint32_t)(((wn*64 + (sel>>1)*8 + lr8)*LDH + (sel&1)*8) * 2);

    float acc[2][8][4];
    #pragma unroll
    for (int mt = 0; mt < 2; mt++)
        #pragma unroll
        for (int nt = 0; nt < 8; nt++)
            #pragma unroll
            for (int i = 0; i < 4; i++) acc[mt][nt][i] = 0.f;

    float4 ra[4];
    int co = tid >> 1, ck0 = (tid & 1) * 16;

    auto ldA = [&](int kc) {
        #pragma unroll
        for (int i = 0; i < 4; i++) {
            int lin = tid + i*256;
            int mm = lin >> 3, kk = (lin & 7) * 4;
            if (AMODE == 0) {
                ra[i] = *(const float4*)(A + (size_t)(m0 + mm) * Ktot + kc + kk);
            } else {
                float4 v = *(const float4*)(A + (size_t)mm * Ktot + kc + kk);
                float4 c = *(const float4*)(ctb + kc + kk);
                v.x *= c.x; v.y *= c.y; v.z *= c.z; v.w *= c.w;
                ra[i] = v;
            }
        }
    };
    auto stA = [&](int buf, int kc) {
        __half* base = Asm + buf*BUFH;
        #pragma unroll
        for (int i = 0; i < 4; i++) {
            int lin = tid + i*256;
            int mm = lin >> 3, kk = (lin & 7) * 4;
            uint2 u;
            u.x = pack_h2(ra[i].x*ascale, ra[i].y*ascale);
            u.y = pack_h2(ra[i].z*ascale, ra[i].w*ascale);
            *(uint2*)(base + mm*LDH + kk) = u;
            if (AMODE == 0 && aout)
                *(uint2*)(aout + (size_t)(m0 + mm) * Ktot + kc + kk) = u;
        }
    };
    auto issueB = [&](int buf, int kc) {
        uint32_t dst = bs_base + buf*BUF_BYTES + (uint32_t)(co*LDH + ck0)*2;
        const __half* src = B16 + (size_t)co * Ktot + kc + ck0;
        CP16(dst,      src);
        CP16(dst + 16, src + 8);
    };
    auto compute = [&](int buf) {
        uint32_t abase = as_base + buf*BUF_BYTES + a_off;
        uint32_t bbase = bs_base + buf*BUF_BYTES + b_off;
        #pragma unroll
        for (int ks = 0; ks < 2; ks++) {
            int kb = ks * 16 * 2;
            uint32_t afr[2][4];
            #pragma unroll
            for (int mt = 0; mt < 2; mt++)
                ldsm4(afr[mt][0], afr[mt][1], afr[mt][2], afr[mt][3],
                      abase + mt*(16*LDH*2) + kb);
            #pragma unroll
            for (int npp = 0; npp < 4; npp++) {
                uint32_t b0, b1, b2, b3;
                ldsm4(b0, b1, b2, b3, bbase + npp*(16*LDH*2) + kb);
                mma_f16(acc[0][2*npp  ], afr[0], b0, b1);
                mma_f16(acc[1][2*npp  ], afr[1], b0, b1);
                mma_f16(acc[0][2*npp+1], afr[0], b2, b3);
                mma_f16(acc[1][2*npp+1], afr[1], b2, b3);
            }
        }
    };

    issueB(0, kc0);
    CP_COMMIT();
    ldA(kc0); stA(0, kc0);
    CP_WAIT0();
    __syncthreads();

    for (int it = 0; it < niter; it++) {
        int cur = it & 1;
        int kcn = kc0 + (it+1)*BLKK;
        if (it + 1 < niter) {
            issueB(1-cur, kcn);
            CP_COMMIT();
            ldA(kcn);
        }
        compute(cur);
        if (it + 1 < niter) {
            stA(1-cur, kcn);
            CP_WAIT0();
        }
        __syncthreads();
    }

    #pragma unroll
    for (int mt = 0; mt < 2; mt++)
        #pragma unroll
        for (int nt = 0; nt < 8; nt++) {
            int row = m0 + wm*32 + mt*16 + lr;
            int col = wn*64 + nt*8 + lc*2;
            float* p = part + ((size_t)blockIdx.z * Mrows + row) * TWOE + col;
            *(float2*)p            = make_float2(acc[mt][nt][0]*inv_ab, acc[mt][nt][1]*inv_ab);
            *(float2*)(p + 8*TWOE) = make_float2(acc[mt][nt][2]*inv_ab, acc[mt][nt][3]*inv_ab);
        }
}

// ---------------- FP16 GEMM, A/B fp16 via cp.async, BLKK=64, 2-stage -----------
__global__ void __launch_bounds__(256) mma_gemm_a16(
        const __half* __restrict__ A16, const __half* __restrict__ B16,
        float* __restrict__ part, int Mrows, int Ktot, int Ksplit, float inv_ab)
{
    extern __shared__ __half hsm[];
    int tid = threadIdx.x;
    int lane = tid & 31, w = tid >> 5;
    int wm = w & 3, wn = w >> 2;
    int lr = lane >> 2, lc = lane & 3;
    int m0 = blockIdx.x * 128;
    int kc0 = blockIdx.z * Ksplit;
    int niter = Ksplit / BLKK2;

    uint32_t as_base = (uint32_t)__cvta_generic_to_shared(hsm);
    uint32_t bs_base = as_base + 2*BUF2_BYTES;
    int sel = lane >> 3, lr8 = lane & 7;
    uint32_t a_off = (uint32_t)(((wm*32 + (sel&1)*8 + lr8)*LDH2 + (sel>>1)*8) * 2);
    uint32_t b_off = (uint32_t)(((wn*64 + (sel>>1)*8 + lr8)*LDH2 + (sel&1)*8) * 2);

    float acc[2][8][4];
    #pragma unroll
    for (int mt = 0; mt < 2; mt++)
        #pragma unroll
        for (int nt = 0; nt < 8; nt++)
            #pragma unroll
            for (int i = 0; i < 4; i++) acc[mt][nt][i] = 0.f;

    int co = tid >> 1, ck0 = (tid & 1) * 32;   // row, 32-half chunk of 64

    auto issueAB = [&](int s, int kc) {
        uint32_t adst = as_base + s*BUF2_BYTES + (uint32_t)(co*LDH2 + ck0)*2;
        const __half* asrc = A16 + (size_t)(m0 + co) * Ktot + kc + ck0;
        #pragma unroll
        for (int j = 0; j < 4; j++) CP16(adst + j*16, asrc + j*8);
        uint32_t bdst = bs_base + s*BUF2_BYTES + (uint32_t)(co*LDH2 + ck0)*2;
        const __half* bsrc = B16 + (size_t)co * Ktot + kc + ck0;
        #pragma unroll
        for (int j = 0; j < 4; j++) CP16(bdst + j*16, bsrc + j*8);
    };
    auto compute = [&](int s) {
        uint32_t abase = as_base + s*BUF2_BYTES + a_off;
        uint32_t bbase = bs_base + s*BUF2_BYTES + b_off;
        #pragma unroll
        for (int ks = 0; ks < 4; ks++) {
            int kb = ks * 16 * 2;
            uint32_t afr[2][4];
            #pragma unroll
            for (int mt = 0; mt < 2; mt++)
                ldsm4(afr[mt][0], afr[mt][1], afr[mt][2], afr[mt][3],
                      abase + mt*(16*LDH2*2) + kb);
            #pragma unroll
            for (int npp = 0; npp < 4; npp++) {
                uint32_t b0, b1, b2, b3;
                ldsm4(b0, b1, b2, b3, bbase + npp*(16*LDH2*2) + kb);
                mma_f16(acc[0][2*npp  ], afr[0], b0, b1);
                mma_f16(acc[1][2*npp  ], afr[1], b0, b1);
                mma_f16(acc[0][2*npp+1], afr[0], b2, b3);
                mma_f16(acc[1][2*npp+1], afr[1], b2, b3);
            }
        }
    };

    // prologue: stages 0 (tile 0) and 1 (tile 1) in flight
    issueAB(0, kc0); CP_COMMIT();
    issueAB(1, kc0 + BLKK2); CP_COMMIT();
    CP_WAIT1();                 // tile 0 landed
    __syncthreads();

    int cur = 0;
    for (int it = 0; it < niter; it++) {
        compute(cur);
        if (it + 2 < niter) {
            issueAB(cur, kc0 + (it+2)*BLKK2);   // reuse just-consumed stage
            CP_COMMIT();
            CP_WAIT1();                          // tile it+1 landed
        } else if (it + 1 < niter) {
            CP_WAIT0();
        }
        __syncthreads();
        cur ^= 1;
    }

    #pragma unroll
    for (int mt = 0; mt < 2; mt++)
        #pragma unroll
        for (int nt = 0; nt < 8; nt++) {
            int row = m0 + wm*32 + mt*16 + lr;
            int col = wn*64 + nt*8 + lc*2;
            float* p = part + ((size_t)blockIdx.z * Mrows + row) * TWOE + col;
            *(float2*)p            = make_float2(acc[mt][nt][0]*inv_ab, acc[mt][nt][1]*inv_ab);
            *(float2*)(p + 8*TWOE) = make_float2(acc[mt][nt][2]*inv_ab, acc[mt][nt][3]*inv_ab);
        }
}

// ---------------- reduce split-K partials + transpose, emit scaled fp16 ----------
__global__ void __launch_bounds__(256) reduceT_k(
        const float* __restrict__ part, const float* __restrict__ W,
        __half* __restrict__ outT, int combine, float oscale)
{
    __shared__ float t[64][65];
    int n0 = blockIdx.x * 64, o0 = blockIdx.y * 64;
    int c0 = threadIdx.x & 63, r4 = threadIdx.x >> 6;
    #pragma unroll
    for (int p = 0; p < 16; p++) {
        int nl = p*4 + r4;
        float s = 0.f;
        #pragma unroll
        for (int z = 0; z < ASPLIT; z++)
            s += part[((size_t)z*NI + n0 + nl)*TWOE + o0 + c0];
        t[nl][c0] = s;
    }
    __syncthreads();
    #pragma unroll
    for (int p = 0; p < 16; p++) {
        int ol = p*4 + r4;
        float v = t[c0][ol];
        if (combine) v = 0.5f*(v + W[(size_t)(o0+ol)*NI + n0 + c0]);
        outT[(size_t)(o0+ol)*NI + n0 + c0] = __float2half_rn(v * oscale);
    }
}

// ---------------- finalize h -> mu / logvar ----------------
__global__ void __launch_bounds__(128) hfinal_k(
        const float* __restrict__ part, int nchunks,
        const float* __restrict__ rnp, const float* __restrict__ bias,
        float* __restrict__ out_mu, float* __restrict__ out_lv)
{
    __shared__ float sq[64];
    __shared__ float sinv, s_rn;
    int kb = blockIdx.x, o = threadIdx.x;
    if (o == 0) {
        float t = 0.f;
        #pragma unroll
        for (int c = 0; c < 8; c++) t += rnp[kb*8 + c];
        s_rn = 1.0f / fmaxf(sqrtf(t), 1e-12f);
    }
    float s = 0.f;
    for (int c = 0; c < nchunks; c++) s += part[(size_t)c*512*TWOE + (size_t)kb*TWOE + o];
    __syncthreads();
    float h = s * s_rn + bias[o];
    if (o < 64) sq[o] = h*h;
    __syncthreads();
    if (o == 0) {
        float t = 0.f;
        #pragma unroll
        for (int i = 0; i < 64; i++) t += sq[i];
        sinv = 1.0f / fmaxf(sqrtf(t), 1e-12f);
    }
    __syncthreads();
    if (o < 64) out_mu[(size_t)kb*EE + o] = h * sinv;
    else        out_lv[(size_t)kb*EE + (o-64)] = -h;
}

// ---------------- decoder (FMA-pipe exp/log polynomials) ----------------
__global__ void __launch_bounds__(256) decoder_k(
        const float* __restrict__ items, const float* __restrict__ cates,
        const float* __restrict__ mu, float* __restrict__ out, int N)
{
    __shared__ float itemsT[64][68];
    __shared__ float mu_s[16][64][4];
    __shared__ float cs[64][4];
    int tid = threadIdx.x;
    int tx = tid & 15, ty = tid >> 4;
    int n0 = blockIdx.x * 64;
    int bt = blockIdx.y * 16;
    #pragma unroll
    for (int i = 0; i < 16; i++) {
        int idx = tid + i*256;
        int n = idx >> 6, e = idx & 63;
        itemsT[e][n] = items[(size_t)(n0+n)*EE + e];
    }
    #pragma unroll
    for (int i = 0; i < 16; i++) {
        int idx = tid + i*256;
        int kb = idx >> 6, e = idx & 63;
        int k = kb >> 4, b = kb & 15;
        mu_s[b][e][k] = mu[(size_t)(k*BB + bt + b)*EE + e];
    }
    {
        int n = tid >> 2, kk = tid & 3;
        cs[n][kk] = cates[(size_t)(n0+n)*KP + kk];
    }
    __syncthreads();

    float acc[4][KP];
    #pragma unroll
    for (int i = 0; i < 4; i++)
        #pragma unroll
        for (int k = 0; k < KP; k++) acc[i][k] = 0.f;

    #pragma unroll 4
    for (int e = 0; e < 64; e++) {
        float4 a = *(const float4*)&itemsT[e][tx*4];
        float4 mm = *(const float4*)&mu_s[ty][e][0];
        float aw[4] = {a.x, a.y, a.z, a.w};
        #pragma unroll
        for (int i = 0; i < 4; i++) {
            acc[i][0] += aw[i]*mm.x; acc[i][1] += aw[i]*mm.y;
            acc[i][2] += aw[i]*mm.z; acc[i][3] += aw[i]*mm.w;
        }
    }
    int b = bt + ty;
    #pragma unroll
    for (int i = 0; i < 4; i++) {
        int nl = tx*4 + i;
        float4 c = *(const float4*)&cs[nl][0];
        float p = exp_t9(acc[i][0])*c.x + exp_t9(acc[i][1])*c.y
                + exp_t9(acc[i][2])*c.z + exp_t9(acc[i][3])*c.w;
        out[(size_t)b*N + n0 + nl] = log_poly(p);
    }
}

// ---------------- launch ----------------
extern "C" void kernel_launch(void* const* d_in, const int* in_sizes, int n_in,
                              void* d_out, int out_size)
{
    const float* x_cf    = (const float*)d_in[0];
    const float* x_tx    = (const float*)d_in[1];
    const float* adj     = (const float*)d_in[2];
    const float* cf_emb  = (const float*)d_in[3];
    const float* cf_prot = (const float*)d_in[4];
    const float* cf_W    = (const float*)d_in[5];
    const float* cf_b    = (const float*)d_in[6];
    const float* tx_emb  = (const float*)d_in[7];
    const float* tx_prot = (const float*)d_in[8];
    const float* tx_W    = (const float*)d_in[9];
    const float* tx_b    = (const float*)d_in[10];
    float* out = (float*)d_out;

    float *p_protos_cf, *p_protos_tx, *p_items_cf, *p_items_tx;
    float *p_cates_cf, *p_cates_tx, *p_ctT_cf, *p_ctT_tx, *p_rnp_cf, *p_rnp_tx;
    float *p_big, *p_part_cf, *p_part_tx;
    __half *p_adj16, *p_W16cf, *p_W16tx, *p_P1T16, *p_MT16;
    cudaGetSymbolAddress((void**)&p_protos_cf, g_protos_cf);
    cudaGetSymbolAddress((void**)&p_protos_tx, g_protos_tx);
    cudaGetSymbolAddress((void**)&p_items_cf,  g_items_cf);
    cudaGetSymbolAddress((void**)&p_items_tx,  g_items_tx);
    cudaGetSymbolAddress((void**)&p_cates_cf,  g_cates_cf);
    cudaGetSymbolAddress((void**)&p_cates_tx,  g_cates_tx);
    cudaGetSymbolAddress((void**)&p_ctT_cf,    g_ctT_cf);
    cudaGetSymbolAddress((void**)&p_ctT_tx,    g_ctT_tx);
    cudaGetSymbolAddress((void**)&p_rnp_cf,    g_rnp_cf);
    cudaGetSymbolAddress((void**)&p_rnp_tx,    g_rnp_tx);
    cudaGetSymbolAddress((void**)&p_adj16,     g_adj16);
    cudaGetSymbolAddress((void**)&p_W16cf,     g_W16cf);
    cudaGetSymbolAddress((void**)&p_W16tx,     g_W16tx);
    cudaGetSymbolAddress((void**)&p_P1T16,     g_P1T16);
    cudaGetSymbolAddress((void**)&p_MT16,      g_MT16);
    cudaGetSymbolAddress((void**)&p_big,       g_bigpart);
    cudaGetSymbolAddress((void**)&p_part_cf,   g_part_cf);
    cudaGetSymbolAddress((void**)&p_part_tx,   g_part_tx);

    static cudaStream_t s_tx = nullptr, s_pre = nullptr;
    static cudaEvent_t ev_fork = nullptr, ev_proto = nullptr, ev_tx = nullptr, ev_pre = nullptr;
    if (!s_tx) {
        cudaStreamCreateWithFlags(&s_tx,  cudaStreamNonBlocking);
        cudaStreamCreateWithFlags(&s_pre, cudaStreamNonBlocking);
        cudaEventCreateWithFlags(&ev_fork,  cudaEventDisableTiming);
        cudaEventCreateWithFlags(&ev_proto, cudaEventDisableTiming);
        cudaEventCreateWithFlags(&ev_tx,    cudaEventDisableTiming);
        cudaEventCreateWithFlags(&ev_pre,   cudaEventDisableTiming);
        cudaFuncSetAttribute(mma_gemm_a16,
            cudaFuncAttributeMaxDynamicSharedMemorySize, SMEM_A16);
    }

    // ---- fork immediately; main stream carries only the adjacency chain ----
    cudaEventRecord(ev_fork, 0);
    cudaStreamWaitEvent(s_pre, ev_fork, 0);
    cudaStreamWaitEvent(s_tx,  ev_fork, 0);

    // ---- s_pre: prototypes + cf prep ----
    proto_norm_k<<<1, 256, 0, s_pre>>>(cf_prot, tx_prot);
    cudaEventRecord(ev_proto, s_pre);
    items_cates_k<<<NI/8, 256, 0, s_pre>>>(cf_emb, p_protos_cf, p_items_cf, p_cates_cf, p_ctT_cf, NI);
    rnormp_k<<<dim3(BB, 8), 256, 0, s_pre>>>(x_cf, p_cates_cf, p_rnp_cf, NI);
    cudaEventRecord(ev_pre, s_pre);

    // ---- s_tx: text branch ----
    convW_k<<<TWOE*NW/4/256, 256, 0, s_tx>>>((const float4*)tx_W, (uint2*)p_W16tx, 64.0f);
    cudaStreamWaitEvent(s_tx, ev_proto, 0);
    items_cates_k<<<NW/8, 256, 0, s_tx>>>(tx_emb, p_protos_tx, p_items_tx, p_cates_tx, p_ctT_tx, NW);
    rnormp_k<<<dim3(BB, 8), 256, 0, s_tx>>>(x_tx, p_cates_tx, p_rnp_tx, NW);
    mma_gemm_t<1><<<dim3(4, 1, HSPLIT), 256, SMEM_GEMM, s_tx>>>(
        x_tx, p_ctT_tx, p_W16tx, p_part_tx, nullptr,
        512, NW, NW/HSPLIT, 16.0f, 1.0f/1024.0f);
    hfinal_k<<<KP*BB, 128, 0, s_tx>>>(p_part_tx, HSPLIT, p_rnp_tx, tx_b,
                                      out + OUT_TXMU, out + OUT_TXLV);
    decoder_k<<<dim3(NW/64, BB/16), 256, 0, s_tx>>>(p_items_tx, p_cates_tx,
                                                    out + OUT_TXMU, out + OUT_TEXT, NW);
    cudaEventRecord(ev_tx, s_tx);

    // ---- main stream: adjacency chain ----
    convW_k<<<TWOE*NI/4/256, 256>>>((const float4*)cf_W, (uint2*)p_W16cf, 64.0f);
    // P1 = adj @ cf_W^T (A fp32, write adj16) -> P1T16
    mma_gemm_t<0><<<dim3(NI/128, 1, ASPLIT), 256, SMEM_GEMM>>>(
        adj, nullptr, p_W16cf, p_big, p_adj16,
        NI, NI, NI/ASPLIT, 4096.0f, 1.0f/(4096.0f*64.0f));
    reduceT_k<<<dim3(NI/64, 2), 256>>>(p_big, nullptr, p_P1T16, 0, 4096.0f);
    // P2 = adj16 @ P1T16 (both fp16, BLKK=64 2-stage cp.async) -> MT16
    mma_gemm_a16<<<dim3(NI/128, 1, ASPLIT), 256, SMEM_A16>>>(
        p_adj16, p_P1T16, p_big, NI, NI, NI/ASPLIT, 1.0f/(4096.0f*4096.0f));
    reduceT_k<<<dim3(NI/64, 2), 256>>>(p_big, cf_W, p_MT16, 1, 64.0f);

    // hpart_cf
    cudaStreamWaitEvent(0, ev_pre, 0);
    mma_gemm_t<1><<<dim3(4, 1, HSPLIT), 256, SMEM_GEMM>>>(
        x_cf, p_ctT_cf, p_MT16, p_part_cf, nullptr,
        512, NI, NI/HSPLIT, 16.0f, 1.0f/1024.0f);
    hfinal_k<<<KP*BB, 128>>>(p_part_cf, HSPLIT, p_rnp_cf, cf_b,
                             out + OUT_CFMU, out + OUT_CFLV);
    decoder_k<<<dim3(NI/64, BB/16), 256>>>(p_items_cf, p_cates_cf,
                                           out + OUT_CFMU, out + OUT_RATING, NI);

    cudaStreamWaitEvent(0, ev_tx, 0);
}

// round 16
// speedup vs baseline: 1.0153x; 1.0153x over previous
#include <cuda_runtime.h>
#include <cuda_fp16.h>
#include <math.h>
#include <stdint.h>

// ---------------- problem constants ----------------
#define BB    128
#define NI    8192
#define NW    16384
#define EE    64
#define KP    4
#define TWOE  128

#define OUT_RATING  0
#define OUT_TEXT    (128*8192)
#define OUT_CFMU    (OUT_TEXT + 128*16384)
#define OUT_CFLV    (OUT_CFMU + 4*128*64)
#define OUT_TXMU    (OUT_CFLV + 4*128*64)
#define OUT_TXLV    (OUT_TXMU + 4*128*64)

#define HSPLIT 32
#define ASPLIT 4

// fp16 mma tile config (128x128)
#define BLKK   32
#define LDH    40                          // halves per smem row (80B, LDSM conflict-free)
#define BUFH   (128*LDH)
#define BUF_BYTES (BUFH*2)                 // 10240
#define SMEM_GEMM (4*BUF_BYTES)            // 2 A + 2 B = 40960
#define SMEM_A16  (6*BUF_BYTES)            // 3 A + 3 B = 61440 (3-stage)

// ---------------- scratch ----------------
__device__ float g_protos_cf[KP*EE];
__device__ float g_protos_tx[KP*EE];
__device__ float g_items_cf[NI*EE];
__device__ float g_items_tx[NW*EE];
__device__ float g_cates_cf[NI*KP];
__device__ float g_cates_tx[NW*KP];
__device__ float g_ctT_cf[KP*NI];
__device__ float g_ctT_tx[KP*NW];
__device__ float g_rnp_cf[KP*BB*8];
__device__ float g_rnp_tx[KP*BB*8];
__device__ __half g_adj16[(size_t)NI*NI];  // adj * 4096, written by P1
__device__ __half g_W16cf[TWOE*NI];        // cf_W * 64
__device__ __half g_W16tx[TWOE*NW];        // tx_W * 64
__device__ __half g_P1T16[TWOE*NI];        // P1^T * 4096
__device__ __half g_MT16 [TWOE*NI];        // M^T  * 64
__device__ __half g_Y16cf[512*NI];         // Y_cf * 16 (fp16)
__device__ float g_bigpart[ASPLIT*NI*TWOE];
__device__ float g_part_cf[HSPLIT*512*TWOE];
__device__ float g_part_tx[HSPLIT*512*TWOE];

// ---------------- helpers ----------------
__device__ __forceinline__ void mma_f16(float c[4], const uint32_t a[4],
                                        uint32_t b0, uint32_t b1) {
    asm volatile(
        "mma.sync.aligned.m16n8k16.row.col.f32.f16.f16.f32 "
        "{%0,%1,%2,%3}, {%4,%5,%6,%7}, {%8,%9}, {%0,%1,%2,%3};"
        : "+f"(c[0]), "+f"(c[1]), "+f"(c[2]), "+f"(c[3])
        : "r"(a[0]), "r"(a[1]), "r"(a[2]), "r"(a[3]), "r"(b0), "r"(b1));
}
__device__ __forceinline__ void ldsm4(uint32_t& r0, uint32_t& r1,
                                      uint32_t& r2, uint32_t& r3, uint32_t addr) {
    asm volatile("ldmatrix.sync.aligned.m8n8.x4.shared.b16 {%0,%1,%2,%3}, [%4];"
                 : "=r"(r0), "=r"(r1), "=r"(r2), "=r"(r3) : "r"(addr));
}
__device__ __forceinline__ uint32_t pack_h2(float a, float b) {
    __half2 h = __floats2half2_rn(a, b);
    return *reinterpret_cast<uint32_t*>(&h);
}
#define CP16(dst, src) \
    asm volatile("cp.async.cg.shared.global [%0], [%1], 16;" :: "r"(dst), "l"(src) : "memory")
#define CP_COMMIT() asm volatile("cp.async.commit_group;" ::: "memory")
#define CP_WAIT0()  asm volatile("cp.async.wait_group 0;" ::: "memory")
#define CP_WAIT1()  asm volatile("cp.async.wait_group 1;" ::: "memory")

// FMA-pipe exp for |x| <= ~1.05 (degree-9 Taylor, rel err ~3e-7)
__device__ __forceinline__ float exp_t9(float x) {
    float r = 2.7557319e-6f;
    r = fmaf(r, x, 2.4801587e-5f);
    r = fmaf(r, x, 1.9841270e-4f);
    r = fmaf(r, x, 1.3888889e-3f);
    r = fmaf(r, x, 8.3333333e-3f);
    r = fmaf(r, x, 4.1666667e-2f);
    r = fmaf(r, x, 1.6666667e-1f);
    r = fmaf(r, x, 0.5f);
    r = fmaf(r, x, 1.0f);
    r = fmaf(r, x, 1.0f);
    return r;
}
// FMA-pipe log (exponent extract + deg-14 log1p, rel err ~1e-7)
__device__ __forceinline__ float log_poly(float p) {
    int ib = __float_as_int(p);
    int e = ((ib >> 23) & 255) - 127;
    float m = __int_as_float((ib & 0x007fffff) | 0x3f800000);
    if (m > 1.4142135f) { m *= 0.5f; e += 1; }
    float u = m - 1.0f;
    float r = -1.0f/14.0f;
    r = fmaf(r, u,  1.0f/13.0f);
    r = fmaf(r, u, -1.0f/12.0f);
    r = fmaf(r, u,  1.0f/11.0f);
    r = fmaf(r, u, -0.1f);
    r = fmaf(r, u,  1.0f/9.0f);
    r = fmaf(r, u, -0.125f);
    r = fmaf(r, u,  1.0f/7.0f);
    r = fmaf(r, u, -1.0f/6.0f);
    r = fmaf(r, u,  0.2f);
    r = fmaf(r, u, -0.25f);
    r = fmaf(r, u,  1.0f/3.0f);
    r = fmaf(r, u, -0.5f);
    r = fmaf(r, u,  1.0f);
    r = r * u;
    return fmaf((float)e, 0.69314718f, r);
}

// ---------------- k0: normalize prototypes ----------------
__global__ void proto_norm_k(const float* __restrict__ cfp, const float* __restrict__ txp) {
    int tid = threadIdx.x;
    int w = tid >> 5, lane = tid & 31;
    const float* src = (w < 4) ? cfp : txp;
    float* dst = (w < 4) ? g_protos_cf : g_protos_tx;
    int row = w & 3;
    float v0 = src[row*EE + lane];
    float v1 = src[row*EE + 32 + lane];
    float s = v0*v0 + v1*v1;
    #pragma unroll
    for (int off = 16; off; off >>= 1) s += __shfl_xor_sync(0xffffffffu, s, off);
    float inv = 1.0f / fmaxf(sqrtf(s), 1e-12f);
    dst[row*EE + lane]      = v0 * inv;
    dst[row*EE + 32 + lane] = v1 * inv;
}

// ---------------- convert W rows to scaled fp16 ----------------
__global__ void __launch_bounds__(256) convW_k(const float4* __restrict__ in,
                                              uint2* __restrict__ out, float scale) {
    int i = blockIdx.x * 256 + threadIdx.x;
    float4 v = in[i];
    uint2 u;
    u.x = pack_h2(v.x*scale, v.y*scale);
    u.y = pack_h2(v.z*scale, v.w*scale);
    out[i] = u;
}

// ---------------- build Y16[kb][n] = x[kb&127][n]*ctT[kb>>7][n]*scale ----------
__global__ void __launch_bounds__(256) buildY_k(
        const float* __restrict__ x, const float* __restrict__ ctT,
        __half* __restrict__ Y16, int N, float scale)
{
    int kb = blockIdx.x;
    int nq = blockIdx.y * 256 + threadIdx.x;        // float4 index within row
    const float4* xr = (const float4*)(x + (size_t)(kb & 127) * N);
    const float4* cr = (const float4*)(ctT + (size_t)(kb >> 7) * N);
    float4 v = xr[nq];
    float4 c = cr[nq];
    uint2 u;
    u.x = pack_h2(v.x*c.x*scale, v.y*c.y*scale);
    u.y = pack_h2(v.z*c.z*scale, v.w*c.w*scale);
    ((uint2*)(Y16 + (size_t)kb * N))[nq] = u;
}

// ---------------- k1: item norm + cates softmax (+ transposed) ----------------
__global__ void __launch_bounds__(256) items_cates_k(
        const float* __restrict__ emb, const float* __restrict__ protos_g,
        float* __restrict__ items_out, float* __restrict__ cates_out,
        float* __restrict__ catesT_out, int N)
{
    __shared__ float ps[KP*EE];
    int tid = threadIdx.x;
    ps[tid] = protos_g[tid];
    __syncthreads();
    int w = tid >> 5, lane = tid & 31;
    int n = blockIdx.x * 8 + w;
    if (n >= N) return;
    float v0 = emb[n*EE + lane];
    float v1 = emb[n*EE + 32 + lane];
    float s = v0*v0 + v1*v1;
    #pragma unroll
    for (int off = 16; off; off >>= 1) s += __shfl_xor_sync(0xffffffffu, s, off);
    float inv = 1.0f / fmaxf(sqrtf(s), 1e-12f);
    float h0 = v0 * inv, h1 = v1 * inv;
    items_out[n*EE + lane]      = h0;
    items_out[n*EE + 32 + lane] = h1;
    float d[KP];
    #pragma unroll
    for (int k = 0; k < KP; k++) {
        float dk = h0 * ps[k*EE + lane] + h1 * ps[k*EE + 32 + lane];
        #pragma unroll
        for (int off = 16; off; off >>= 1) dk += __shfl_xor_sync(0xffffffffu, dk, off);
        d[k] = dk;
    }
    if (lane == 0) {
        float m = fmaxf(fmaxf(d[0], d[1]), fmaxf(d[2], d[3]));
        float e0 = __expf(d[0]-m), e1 = __expf(d[1]-m), e2 = __expf(d[2]-m), e3 = __expf(d[3]-m);
        float is = 1.0f / (e0+e1+e2+e3);
        float c0 = e0*is, c1 = e1*is, c2 = e2*is, c3 = e3*is;
        *(float4*)&cates_out[n*KP] = make_float4(c0, c1, c2, c3);
        catesT_out[0*N + n] = c0;
        catesT_out[1*N + n] = c1;
        catesT_out[2*N + n] = c2;
        catesT_out[3*N + n] = c3;
    }
}

// ---------------- k2: rnorm partials ----------------
__global__ void __launch_bounds__(256) rnormp_k(
        const float* __restrict__ x, const float* __restrict__ cates,
        float* __restrict__ rnp, int N)
{
    __shared__ float red[8][KP];
    int b = blockIdx.x, chunk = blockIdx.y, tid = threadIdx.x;
    int n0 = chunk * (N >> 3), n1 = n0 + (N >> 3);
    float s0=0.f, s1=0.f, s2=0.f, s3=0.f;
    const float* xr = x + (size_t)b * N;
    for (int n = n0 + tid; n < n1; n += 256) {
        float xv = xr[n];
        float4 c = *(const float4*)&cates[n*KP];
        float t0 = xv*c.x, t1 = xv*c.y, t2 = xv*c.z, t3 = xv*c.w;
        s0 += t0*t0; s1 += t1*t1; s2 += t2*t2; s3 += t3*t3;
    }
    #pragma unroll
    for (int off = 16; off; off >>= 1) {
        s0 += __shfl_xor_sync(0xffffffffu, s0, off);
        s1 += __shfl_xor_sync(0xffffffffu, s1, off);
        s2 += __shfl_xor_sync(0xffffffffu, s2, off);
        s3 += __shfl_xor_sync(0xffffffffu, s3, off);
    }
    int w = tid >> 5;
    if ((tid & 31) == 0) { red[w][0]=s0; red[w][1]=s1; red[w][2]=s2; red[w][3]=s3; }
    __syncthreads();
    if (tid < KP) {
        float t = 0.f;
        #pragma unroll
        for (int i = 0; i < 8; i++) t += red[i][tid];
        rnp[(tid*BB + b)*8 + chunk] = t;
    }
}

// ---------------- FP16 MMA GEMM (templated A-mode), B fp16 via cp.async --------
// AMODE 0: A fp32 rows, cvt*ascale in producer; optional fp16 write-through to aout
// AMODE 1: A = x[m][n]*ctT[bx][n] on the fly
template<int AMODE>
__global__ void __launch_bounds__(256) mma_gemm_t(
        const float* __restrict__ A, const float* __restrict__ ctT,
        const __half* __restrict__ B16,
        float* __restrict__ part, __half* __restrict__ aout,
        int Mrows, int Ktot, int Ksplit, float ascale, float inv_ab)
{
    extern __shared__ __half hsm[];
    __half* Asm = hsm;
    int tid = threadIdx.x;
    int lane = tid & 31, w = tid >> 5;
    int wm = w & 3, wn = w >> 2;
    int lr = lane >> 2, lc = lane & 3;
    int m0 = blockIdx.x * 128;
    int kc0 = blockIdx.z * Ksplit;
    int niter = Ksplit / BLKK;
    const float* ctb = (AMODE == 1) ? (ctT + (size_t)blockIdx.x * Ktot) : (const float*)0;

    uint32_t as_base = (uint32_t)__cvta_generic_to_shared(Asm);
    uint32_t bs_base = as_base + 2*BUF_BYTES;
    int sel = lane >> 3, lr8 = lane & 7;
    uint32_t a_off = (uint32_t)(((wm*32 + (sel&1)*8 + lr8)*LDH + (sel>>1)*8) * 2);
    uint32_t b_off = (uint32_t)(((wn*64 + (sel>>1)*8 + lr8)*LDH + (sel&1)*8) * 2);

    float acc[2][8][4];
    #pragma unroll
    for (int mt = 0; mt < 2; mt++)
        #pragma unroll
        for (int nt = 0; nt < 8; nt++)
            #pragma unroll
            for (int i = 0; i < 4; i++) acc[mt][nt][i] = 0.f;

    float4 ra[4];
    int co = tid >> 1, ck0 = (tid & 1) * 16;

    auto ldA = [&](int kc) {
        #pragma unroll
        for (int i = 0; i < 4; i++) {
            int lin = tid + i*256;
            int mm = lin >> 3, kk = (lin & 7) * 4;
            if (AMODE == 0) {
                ra[i] = *(const float4*)(A + (size_t)(m0 + mm) * Ktot + kc + kk);
            } else {
                float4 v = *(const float4*)(A + (size_t)mm * Ktot + kc + kk);
                float4 c = *(const float4*)(ctb + kc + kk);
                v.x *= c.x; v.y *= c.y; v.z *= c.z; v.w *= c.w;
                ra[i] = v;
            }
        }
    };
    auto stA = [&](int buf, int kc) {
        __half* base = Asm + buf*BUFH;
        #pragma unroll
        for (int i = 0; i < 4; i++) {
            int lin = tid + i*256;
            int mm = lin >> 3, kk = (lin & 7) * 4;
            uint2 u;
            u.x = pack_h2(ra[i].x*ascale, ra[i].y*ascale);
            u.y = pack_h2(ra[i].z*ascale, ra[i].w*ascale);
            *(uint2*)(base + mm*LDH + kk) = u;
            if (AMODE == 0 && aout)
                *(uint2*)(aout + (size_t)(m0 + mm) * Ktot + kc + kk) = u;
        }
    };
    auto issueB = [&](int buf, int kc) {
        uint32_t dst = bs_base + buf*BUF_BYTES + (uint32_t)(co*LDH + ck0)*2;
        const __half* src = B16 + (size_t)co * Ktot + kc + ck0;
        CP16(dst,      src);
        CP16(dst + 16, src + 8);
    };
    auto compute = [&](int buf) {
        uint32_t abase = as_base + buf*BUF_BYTES + a_off;
        uint32_t bbase = bs_base + buf*BUF_BYTES + b_off;
        #pragma unroll
        for (int ks = 0; ks < 2; ks++) {
            int kb = ks * 16 * 2;
            uint32_t afr[2][4];
            #pragma unroll
            for (int mt = 0; mt < 2; mt++)
                ldsm4(afr[mt][0], afr[mt][1], afr[mt][2], afr[mt][3],
                      abase + mt*(16*LDH*2) + kb);
            #pragma unroll
            for (int npp = 0; npp < 4; npp++) {
                uint32_t b0, b1, b2, b3;
                ldsm4(b0, b1, b2, b3, bbase + npp*(16*LDH*2) + kb);
                mma_f16(acc[0][2*npp  ], afr[0], b0, b1);
                mma_f16(acc[1][2*npp  ], afr[1], b0, b1);
                mma_f16(acc[0][2*npp+1], afr[0], b2, b3);
                mma_f16(acc[1][2*npp+1], afr[1], b2, b3);
            }
        }
    };

    issueB(0, kc0);
    CP_COMMIT();
    ldA(kc0); stA(0, kc0);
    CP_WAIT0();
    __syncthreads();

    for (int it = 0; it < niter; it++) {
        int cur = it & 1;
        int kcn = kc0 + (it+1)*BLKK;
        if (it + 1 < niter) {
            issueB(1-cur, kcn);
            CP_COMMIT();
            ldA(kcn);
        }
        compute(cur);
        if (it + 1 < niter) {
            stA(1-cur, kcn);
            CP_WAIT0();
        }
        __syncthreads();
    }

    #pragma unroll
    for (int mt = 0; mt < 2; mt++)
        #pragma unroll
        for (int nt = 0; nt < 8; nt++) {
            int row = m0 + wm*32 + mt*16 + lr;
            int col = wn*64 + nt*8 + lc*2;
            float* p = part + ((size_t)blockIdx.z * Mrows + row) * TWOE + col;
            *(float2*)p            = make_float2(acc[mt][nt][0]*inv_ab, acc[mt][nt][1]*inv_ab);
            *(float2*)(p + 8*TWOE) = make_float2(acc[mt][nt][2]*inv_ab, acc[mt][nt][3]*inv_ab);
        }
}

// ---------------- FP16 GEMM, A and B fp16 via cp.async, 3-stage pipeline -------
__global__ void __launch_bounds__(256) mma_gemm_a16(
        const __half* __restrict__ A16, const __half* __restrict__ B16,
        float* __restrict__ part, int Mrows, int Ktot, int Ksplit, float inv_ab)
{
    extern __shared__ __half hsm[];
    int tid = threadIdx.x;
    int lane = tid & 31, w = tid >> 5;
    int wm = w & 3, wn = w >> 2;
    int lr = lane >> 2, lc = lane & 3;
    int m0 = blockIdx.x * 128;
    int kc0 = blockIdx.z * Ksplit;
    int niter = Ksplit / BLKK;

    uint32_t as_base = (uint32_t)__cvta_generic_to_shared(hsm);
    uint32_t bs_base = as_base + 3*BUF_BYTES;
    int sel = lane >> 3, lr8 = lane & 7;
    uint32_t a_off = (uint32_t)(((wm*32 + (sel&1)*8 + lr8)*LDH + (sel>>1)*8) * 2);
    uint32_t b_off = (uint32_t)(((wn*64 + (sel>>1)*8 + lr8)*LDH + (sel&1)*8) * 2);

    float acc[2][8][4];
    #pragma unroll
    for (int mt = 0; mt < 2; mt++)
        #pragma unroll
        for (int nt = 0; nt < 8; nt++)
            #pragma unroll
            for (int i = 0; i < 4; i++) acc[mt][nt][i] = 0.f;

    int co = tid >> 1, ck0 = (tid & 1) * 16;

    auto issueAB = [&](int s, int kc) {
        uint32_t adst = as_base + s*BUF_BYTES + (uint32_t)(co*LDH + ck0)*2;
        const __half* asrc = A16 + (size_t)(m0 + co) * Ktot + kc + ck0;
        CP16(adst,      asrc);
        CP16(adst + 16, asrc + 8);
        uint32_t bdst = bs_base + s*BUF_BYTES + (uint32_t)(co*LDH + ck0)*2;
        const __half* bsrc = B16 + (size_t)co * Ktot + kc + ck0;
        CP16(bdst,      bsrc);
        CP16(bdst + 16, bsrc + 8);
    };
    auto compute = [&](int s) {
        uint32_t abase = as_base + s*BUF_BYTES + a_off;
        uint32_t bbase = bs_base + s*BUF_BYTES + b_off;
        #pragma unroll
        for (int ks = 0; ks < 2; ks++) {
            int kb = ks * 16 * 2;
            uint32_t afr[2][4];
            #pragma unroll
            for (int mt = 0; mt < 2; mt++)
                ldsm4(afr[mt][0], afr[mt][1], afr[mt][2], afr[mt][3],
                      abase + mt*(16*LDH*2) + kb);
            #pragma unroll
            for (int npp = 0; npp < 4; npp++) {
                uint32_t b0, b1, b2, b3;
                ldsm4(b0, b1, b2, b3, bbase + npp*(16*LDH*2) + kb);
                mma_f16(acc[0][2*npp  ], afr[0], b0, b1);
                mma_f16(acc[1][2*npp  ], afr[1], b0, b1);
                mma_f16(acc[0][2*npp+1], afr[0], b2, b3);
                mma_f16(acc[1][2*npp+1], afr[1], b2, b3);
            }
        }
    };

    issueAB(0, kc0); CP_COMMIT();
    issueAB(1, kc0 + BLKK); CP_COMMIT();
    CP_WAIT1();
    __syncthreads();

    int cur = 0;
    for (int it = 0; it < niter; it++) {
        if (it + 2 < niter) { issueAB((cur + 2) % 3, kc0 + (it+2)*BLKK); CP_COMMIT(); }
        compute(cur);
        if (it + 2 < niter)      CP_WAIT1();
        else if (it + 1 < niter) CP_WAIT0();
        __syncthreads();
        if (++cur == 3) cur = 0;
    }

    #pragma unroll
    for (int mt = 0; mt < 2; mt++)
        #pragma unroll
        for (int nt = 0; nt < 8; nt++) {
            int row = m0 + wm*32 + mt*16 + lr;
            int col = wn*64 + nt*8 + lc*2;
            float* p = part + ((size_t)blockIdx.z * Mrows + row) * TWOE + col;
            *(float2*)p            = make_float2(acc[mt][nt][0]*inv_ab, acc[mt][nt][1]*inv_ab);
            *(float2*)(p + 8*TWOE) = make_float2(acc[mt][nt][2]*inv_ab, acc[mt][nt][3]*inv_ab);
        }
}

// ---------------- reduce split-K partials + transpose, emit scaled fp16 ----------
__global__ void __launch_bounds__(256) reduceT_k(
        const float* __restrict__ part, const float* __restrict__ W,
        __half* __restrict__ outT, int combine, float oscale)
{
    __shared__ float t[64][65];
    int n0 = blockIdx.x * 64, o0 = blockIdx.y * 64;
    int c0 = threadIdx.x & 63, r4 = threadIdx.x >> 6;
    #pragma unroll
    for (int p = 0; p < 16; p++) {
        int nl = p*4 + r4;
        float s = 0.f;
        #pragma unroll
        for (int z = 0; z < ASPLIT; z++)
            s += part[((size_t)z*NI + n0 + nl)*TWOE + o0 + c0];
        t[nl][c0] = s;
    }
    __syncthreads();
    #pragma unroll
    for (int p = 0; p < 16; p++) {
        int ol = p*4 + r4;
        float v = t[c0][ol];
        if (combine) v = 0.5f*(v + W[(size_t)(o0+ol)*NI + n0 + c0]);
        outT[(size_t)(o0+ol)*NI + n0 + c0] = __float2half_rn(v * oscale);
    }
}

// ---------------- finalize h -> mu / logvar ----------------
__global__ void __launch_bounds__(128) hfinal_k(
        const float* __restrict__ part, int nchunks,
        const float* __restrict__ rnp, const float* __restrict__ bias,
        float* __restrict__ out_mu, float* __restrict__ out_lv)
{
    __shared__ float sq[64];
    __shared__ float sinv, s_rn;
    int kb = blockIdx.x, o = threadIdx.x;
    if (o == 0) {
        float t = 0.f;
        #pragma unroll
        for (int c = 0; c < 8; c++) t += rnp[kb*8 + c];
        s_rn = 1.0f / fmaxf(sqrtf(t), 1e-12f);
    }
    float s = 0.f;
    for (int c = 0; c < nchunks; c++) s += part[(size_t)c*512*TWOE + (size_t)kb*TWOE + o];
    __syncthreads();
    float h = s * s_rn + bias[o];
    if (o < 64) sq[o] = h*h;
    __syncthreads();
    if (o == 0) {
        float t = 0.f;
        #pragma unroll
        for (int i = 0; i < 64; i++) t += sq[i];
        sinv = 1.0f / fmaxf(sqrtf(t), 1e-12f);
    }
    __syncthreads();
    if (o < 64) out_mu[(size_t)kb*EE + o] = h * sinv;
    else        out_lv[(size_t)kb*EE + (o-64)] = -h;
}

// ---------------- decoder (FMA-pipe exp/log polynomials) ----------------
__global__ void __launch_bounds__(256) decoder_k(
        const float* __restrict__ items, const float* __restrict__ cates,
        const float* __restrict__ mu, float* __restrict__ out, int N)
{
    __shared__ float itemsT[64][68];
    __shared__ float mu_s[16][64][4];
    __shared__ float cs[64][4];
    int tid = threadIdx.x;
    int tx = tid & 15, ty = tid >> 4;
    int n0 = blockIdx.x * 64;
    int bt = blockIdx.y * 16;
    #pragma unroll
    for (int i = 0; i < 16; i++) {
        int idx = tid + i*256;
        int n = idx >> 6, e = idx & 63;
        itemsT[e][n] = items[(size_t)(n0+n)*EE + e];
    }
    #pragma unroll
    for (int i = 0; i < 16; i++) {
        int idx = tid + i*256;
        int kb = idx >> 6, e = idx & 63;
        int k = kb >> 4, b = kb & 15;
        mu_s[b][e][k] = mu[(size_t)(k*BB + bt + b)*EE + e];
    }
    {
        int n = tid >> 2, kk = tid & 3;
        cs[n][kk] = cates[(size_t)(n0+n)*KP + kk];
    }
    __syncthreads();

    float acc[4][KP];
    #pragma unroll
    for (int i = 0; i < 4; i++)
        #pragma unroll
        for (int k = 0; k < KP; k++) acc[i][k] = 0.f;

    #pragma unroll 4
    for (int e = 0; e < 64; e++) {
        float4 a = *(const float4*)&itemsT[e][tx*4];
        float4 mm = *(const float4*)&mu_s[ty][e][0];
        float aw[4] = {a.x, a.y, a.z, a.w};
        #pragma unroll
        for (int i = 0; i < 4; i++) {
            acc[i][0] += aw[i]*mm.x; acc[i][1] += aw[i]*mm.y;
            acc[i][2] += aw[i]*mm.z; acc[i][3] += aw[i]*mm.w;
        }
    }
    int b = bt + ty;
    #pragma unroll
    for (int i = 0; i < 4; i++) {
        int nl = tx*4 + i;
        float4 c = *(const float4*)&cs[nl][0];
        float p = exp_t9(acc[i][0])*c.x + exp_t9(acc[i][1])*c.y
                + exp_t9(acc[i][2])*c.z + exp_t9(acc[i][3])*c.w;
        out[(size_t)b*N + n0 + nl] = log_poly(p);
    }
}

// ---------------- launch ----------------
extern "C" void kernel_launch(void* const* d_in, const int* in_sizes, int n_in,
                              void* d_out, int out_size)
{
    const float* x_cf    = (const float*)d_in[0];
    const float* x_tx    = (const float*)d_in[1];
    const float* adj     = (const float*)d_in[2];
    const float* cf_emb  = (const float*)d_in[3];
    const float* cf_prot = (const float*)d_in[4];
    const float* cf_W    = (const float*)d_in[5];
    const float* cf_b    = (const float*)d_in[6];
    const float* tx_emb  = (const float*)d_in[7];
    const float* tx_prot = (const float*)d_in[8];
    const float* tx_W    = (const float*)d_in[9];
    const float* tx_b    = (const float*)d_in[10];
    float* out = (float*)d_out;

    float *p_protos_cf, *p_protos_tx, *p_items_cf, *p_items_tx;
    float *p_cates_cf, *p_cates_tx, *p_ctT_cf, *p_ctT_tx, *p_rnp_cf, *p_rnp_tx;
    float *p_big, *p_part_cf, *p_part_tx;
    __half *p_adj16, *p_W16cf, *p_W16tx, *p_P1T16, *p_MT16, *p_Y16cf;
    cudaGetSymbolAddress((void**)&p_protos_cf, g_protos_cf);
    cudaGetSymbolAddress((void**)&p_protos_tx, g_protos_tx);
    cudaGetSymbolAddress((void**)&p_items_cf,  g_items_cf);
    cudaGetSymbolAddress((void**)&p_items_tx,  g_items_tx);
    cudaGetSymbolAddress((void**)&p_cates_cf,  g_cates_cf);
    cudaGetSymbolAddress((void**)&p_cates_tx,  g_cates_tx);
    cudaGetSymbolAddress((void**)&p_ctT_cf,    g_ctT_cf);
    cudaGetSymbolAddress((void**)&p_ctT_tx,    g_ctT_tx);
    cudaGetSymbolAddress((void**)&p_rnp_cf,    g_rnp_cf);
    cudaGetSymbolAddress((void**)&p_rnp_tx,    g_rnp_tx);
    cudaGetSymbolAddress((void**)&p_adj16,     g_adj16);
    cudaGetSymbolAddress((void**)&p_W16cf,     g_W16cf);
    cudaGetSymbolAddress((void**)&p_W16tx,     g_W16tx);
    cudaGetSymbolAddress((void**)&p_P1T16,     g_P1T16);
    cudaGetSymbolAddress((void**)&p_MT16,      g_MT16);
    cudaGetSymbolAddress((void**)&p_Y16cf,     g_Y16cf);
    cudaGetSymbolAddress((void**)&p_big,       g_bigpart);
    cudaGetSymbolAddress((void**)&p_part_cf,   g_part_cf);
    cudaGetSymbolAddress((void**)&p_part_tx,   g_part_tx);

    static cudaStream_t s_tx = nullptr, s_pre = nullptr;
    static cudaEvent_t ev_fork = nullptr, ev_proto = nullptr, ev_tx = nullptr, ev_pre = nullptr;
    if (!s_tx) {
        cudaStreamCreateWithFlags(&s_tx,  cudaStreamNonBlocking);
        cudaStreamCreateWithFlags(&s_pre, cudaStreamNonBlocking);
        cudaEventCreateWithFlags(&ev_fork,  cudaEventDisableTiming);
        cudaEventCreateWithFlags(&ev_proto, cudaEventDisableTiming);
        cudaEventCreateWithFlags(&ev_tx,    cudaEventDisableTiming);
        cudaEventCreateWithFlags(&ev_pre,   cudaEventDisableTiming);
        cudaFuncSetAttribute(mma_gemm_a16,
            cudaFuncAttributeMaxDynamicSharedMemorySize, SMEM_A16);
    }

    // ---- fork immediately; main stream carries only the adjacency chain ----
    cudaEventRecord(ev_fork, 0);
    cudaStreamWaitEvent(s_pre, ev_fork, 0);
    cudaStreamWaitEvent(s_tx,  ev_fork, 0);

    // ---- s_pre: prototypes + cf prep + Y16 build ----
    proto_norm_k<<<1, 256, 0, s_pre>>>(cf_prot, tx_prot);
    cudaEventRecord(ev_proto, s_pre);
    items_cates_k<<<NI/8, 256, 0, s_pre>>>(cf_emb, p_protos_cf, p_items_cf, p_cates_cf, p_ctT_cf, NI);
    rnormp_k<<<dim3(BB, 8), 256, 0, s_pre>>>(x_cf, p_cates_cf, p_rnp_cf, NI);
    buildY_k<<<dim3(512, NI/1024), 256, 0, s_pre>>>(x_cf, p_ctT_cf, p_Y16cf, NI, 16.0f);
    cudaEventRecord(ev_pre, s_pre);

    // ---- s_tx: text branch ----
    convW_k<<<TWOE*NW/4/256, 256, 0, s_tx>>>((const float4*)tx_W, (uint2*)p_W16tx, 64.0f);
    cudaStreamWaitEvent(s_tx, ev_proto, 0);
    items_cates_k<<<NW/8, 256, 0, s_tx>>>(tx_emb, p_protos_tx, p_items_tx, p_cates_tx, p_ctT_tx, NW);
    rnormp_k<<<dim3(BB, 8), 256, 0, s_tx>>>(x_tx, p_cates_tx, p_rnp_tx, NW);
    mma_gemm_t<1><<<dim3(4, 1, HSPLIT), 256, SMEM_GEMM, s_tx>>>(
        x_tx, p_ctT_tx, p_W16tx, p_part_tx, nullptr,
        512, NW, NW/HSPLIT, 16.0f, 1.0f/1024.0f);
    hfinal_k<<<KP*BB, 128, 0, s_tx>>>(p_part_tx, HSPLIT, p_rnp_tx, tx_b,
                                      out + OUT_TXMU, out + OUT_TXLV);
    decoder_k<<<dim3(NW/64, BB/16), 256, 0, s_tx>>>(p_items_tx, p_cates_tx,
                                                    out + OUT_TXMU, out + OUT_TEXT, NW);
    cudaEventRecord(ev_tx, s_tx);

    // ---- main stream: adjacency chain ----
    convW_k<<<TWOE*NI/4/256, 256>>>((const float4*)cf_W, (uint2*)p_W16cf, 64.0f);
    // P1 = adj @ cf_W^T (A fp32, write adj16) -> P1T16
    mma_gemm_t<0><<<dim3(NI/128, 1, ASPLIT), 256, SMEM_GEMM>>>(
        adj, nullptr, p_W16cf, p_big, p_adj16,
        NI, NI, NI/ASPLIT, 4096.0f, 1.0f/(4096.0f*64.0f));
    reduceT_k<<<dim3(NI/64, 2), 256>>>(p_big, nullptr, p_P1T16, 0, 4096.0f);
    // P2 = adj16 @ P1T16 (both fp16, 3-stage cp.async) -> MT16
    mma_gemm_a16<<<dim3(NI/128, 1, ASPLIT), 256, SMEM_A16>>>(
        p_adj16, p_P1T16, p_big, NI, NI, NI/ASPLIT, 1.0f/(4096.0f*4096.0f));
    reduceT_k<<<dim3(NI/64, 2), 256>>>(p_big, cf_W, p_MT16, 1, 64.0f);

    // hpart_cf: pure fp16 cp.async GEMM on precomputed Y16
    cudaStreamWaitEvent(0, ev_pre, 0);
    mma_gemm_a16<<<dim3(4, 1, HSPLIT), 256, SMEM_A16>>>(
        p_Y16cf, p_MT16, p_part_cf, 512, NI, NI/HSPLIT, 1.0f/1024.0f);
    hfinal_k<<<KP*BB, 128>>>(p_part_cf, HSPLIT, p_rnp_cf, cf_b,
                             out + OUT_CFMU, out + OUT_CFLV);
    decoder_k<<<dim3(NI/64, BB/16), 256>>>(p_items_cf, p_cates_cf,
                                           out + OUT_CFMU, out + OUT_RATING, NI);

    cudaStreamWaitEvent(0, ev_tx, 0);
}

// round 17
// speedup vs baseline: 1.0472x; 1.0315x over previous
#include <cuda_runtime.h>
#include <cuda_fp16.h>
#include <math.h>
#include <stdint.h>

// ---------------- problem constants ----------------
#define BB    128
#define NI    8192
#define NW    16384
#define EE    64
#define KP    4
#define TWOE  128

#define OUT_RATING  0
#define OUT_TEXT    (128*8192)
#define OUT_CFMU    (OUT_TEXT + 128*16384)
#define OUT_CFLV    (OUT_CFMU + 4*128*64)
#define OUT_TXMU    (OUT_CFLV + 4*128*64)
#define OUT_TXLV    (OUT_TXMU + 4*128*64)

#define HSPLIT 32
#define ASPLIT 4

// fp16 mma tile config (128x128)
#define BLKK   32
#define LDH    40                          // halves per smem row (80B, LDSM conflict-free)
#define BUFH   (128*LDH)
#define BUF_BYTES (BUFH*2)                 // 10240
#define SMEM_GEMM (4*BUF_BYTES)            // 2 A + 2 B = 40960
#define SMEM_A16  (8*BUF_BYTES)            // 4 A + 4 B = 81920 (4-stage)

// ---------------- scratch ----------------
__device__ float g_protos_cf[KP*EE];
__device__ float g_protos_tx[KP*EE];
__device__ float g_items_cf[NI*EE];
__device__ float g_items_tx[NW*EE];
__device__ float g_cates_cf[NI*KP];
__device__ float g_cates_tx[NW*KP];
__device__ float g_ctT_cf[KP*NI];
__device__ float g_ctT_tx[KP*NW];
__device__ float g_rnp_cf[KP*BB*8];
__device__ float g_rnp_tx[KP*BB*8];
__device__ __half g_adj16[(size_t)NI*NI];  // adj * 4096, written by P1
__device__ __half g_W16cf[TWOE*NI];        // cf_W * 64
__device__ __half g_W16tx[TWOE*NW];        // tx_W * 64
__device__ __half g_P1T16[TWOE*NI];        // P1^T * 4096
__device__ __half g_MT16 [TWOE*NI];        // M^T  * 64
__device__ __half g_Y16cf[512*NI];         // Y_cf * 16 (fp16)
__device__ float g_bigpart[ASPLIT*NI*TWOE];
__device__ float g_part_cf[HSPLIT*512*TWOE];
__device__ float g_part_tx[HSPLIT*512*TWOE];

// ---------------- helpers ----------------
__device__ __forceinline__ void mma_f16(float c[4], const uint32_t a[4],
                                        uint32_t b0, uint32_t b1) {
    asm volatile(
        "mma.sync.aligned.m16n8k16.row.col.f32.f16.f16.f32 "
        "{%0,%1,%2,%3}, {%4,%5,%6,%7}, {%8,%9}, {%0,%1,%2,%3};"
        : "+f"(c[0]), "+f"(c[1]), "+f"(c[2]), "+f"(c[3])
        : "r"(a[0]), "r"(a[1]), "r"(a[2]), "r"(a[3]), "r"(b0), "r"(b1));
}
__device__ __forceinline__ void ldsm4(uint32_t& r0, uint32_t& r1,
                                      uint32_t& r2, uint32_t& r3, uint32_t addr) {
    asm volatile("ldmatrix.sync.aligned.m8n8.x4.shared.b16 {%0,%1,%2,%3}, [%4];"
                 : "=r"(r0), "=r"(r1), "=r"(r2), "=r"(r3) : "r"(addr));
}
__device__ __forceinline__ uint32_t pack_h2(float a, float b) {
    __half2 h = __floats2half2_rn(a, b);
    return *reinterpret_cast<uint32_t*>(&h);
}
#define CP16(dst, src) \
    asm volatile("cp.async.cg.shared.global [%0], [%1], 16;" :: "r"(dst), "l"(src) : "memory")
#define CP_COMMIT() asm volatile("cp.async.commit_group;" ::: "memory")
#define CP_WAIT0()  asm volatile("cp.async.wait_group 0;" ::: "memory")
#define CP_WAIT1()  asm volatile("cp.async.wait_group 1;" ::: "memory")
#define CP_WAIT2()  asm volatile("cp.async.wait_group 2;" ::: "memory")

// FMA-pipe exp for |x| <= ~1.05 (degree-9 Taylor, rel err ~3e-7)
__device__ __forceinline__ float exp_t9(float x) {
    float r = 2.7557319e-6f;
    r = fmaf(r, x, 2.4801587e-5f);
    r = fmaf(r, x, 1.9841270e-4f);
    r = fmaf(r, x, 1.3888889e-3f);
    r = fmaf(r, x, 8.3333333e-3f);
    r = fmaf(r, x, 4.1666667e-2f);
    r = fmaf(r, x, 1.6666667e-1f);
    r = fmaf(r, x, 0.5f);
    r = fmaf(r, x, 1.0f);
    r = fmaf(r, x, 1.0f);
    return r;
}
// FMA-pipe log (exponent extract + deg-14 log1p, rel err ~1e-7)
__device__ __forceinline__ float log_poly(float p) {
    int ib = __float_as_int(p);
    int e = ((ib >> 23) & 255) - 127;
    float m = __int_as_float((ib & 0x007fffff) | 0x3f800000);
    if (m > 1.4142135f) { m *= 0.5f; e += 1; }
    float u = m - 1.0f;
    float r = -1.0f/14.0f;
    r = fmaf(r, u,  1.0f/13.0f);
    r = fmaf(r, u, -1.0f/12.0f);
    r = fmaf(r, u,  1.0f/11.0f);
    r = fmaf(r, u, -0.1f);
    r = fmaf(r, u,  1.0f/9.0f);
    r = fmaf(r, u, -0.125f);
    r = fmaf(r, u,  1.0f/7.0f);
    r = fmaf(r, u, -1.0f/6.0f);
    r = fmaf(r, u,  0.2f);
    r = fmaf(r, u, -0.25f);
    r = fmaf(r, u,  1.0f/3.0f);
    r = fmaf(r, u, -0.5f);
    r = fmaf(r, u,  1.0f);
    r = r * u;
    return fmaf((float)e, 0.69314718f, r);
}

// ---------------- k0: normalize prototypes ----------------
__global__ void proto_norm_k(const float* __restrict__ cfp, const float* __restrict__ txp) {
    int tid = threadIdx.x;
    int w = tid >> 5, lane = tid & 31;
    const float* src = (w < 4) ? cfp : txp;
    float* dst = (w < 4) ? g_protos_cf : g_protos_tx;
    int row = w & 3;
    float v0 = src[row*EE + lane];
    float v1 = src[row*EE + 32 + lane];
    float s = v0*v0 + v1*v1;
    #pragma unroll
    for (int off = 16; off; off >>= 1) s += __shfl_xor_sync(0xffffffffu, s, off);
    float inv = 1.0f / fmaxf(sqrtf(s), 1e-12f);
    dst[row*EE + lane]      = v0 * inv;
    dst[row*EE + 32 + lane] = v1 * inv;
}

// ---------------- convert W rows to scaled fp16 ----------------
__global__ void __launch_bounds__(256) convW_k(const float4* __restrict__ in,
                                              uint2* __restrict__ out, float scale) {
    int i = blockIdx.x * 256 + threadIdx.x;
    float4 v = in[i];
    uint2 u;
    u.x = pack_h2(v.x*scale, v.y*scale);
    u.y = pack_h2(v.z*scale, v.w*scale);
    out[i] = u;
}

// ---------------- build Y16[kb][n] = x[kb&127][n]*ctT[kb>>7][n]*scale ----------
__global__ void __launch_bounds__(256) buildY_k(
        const float* __restrict__ x, const float* __restrict__ ctT,
        __half* __restrict__ Y16, int N, float scale)
{
    int kb = blockIdx.x;
    int nq = blockIdx.y * 256 + threadIdx.x;
    const float4* xr = (const float4*)(x + (size_t)(kb & 127) * N);
    const float4* cr = (const float4*)(ctT + (size_t)(kb >> 7) * N);
    float4 v = xr[nq];
    float4 c = cr[nq];
    uint2 u;
    u.x = pack_h2(v.x*c.x*scale, v.y*c.y*scale);
    u.y = pack_h2(v.z*c.z*scale, v.w*c.w*scale);
    ((uint2*)(Y16 + (size_t)kb * N))[nq] = u;
}

// ---------------- k1: item norm + cates softmax (+ transposed) ----------------
__global__ void __launch_bounds__(256) items_cates_k(
        const float* __restrict__ emb, const float* __restrict__ protos_g,
        float* __restrict__ items_out, float* __restrict__ cates_out,
        float* __restrict__ catesT_out, int N)
{
    __shared__ float ps[KP*EE];
    int tid = threadIdx.x;
    ps[tid] = protos_g[tid];
    __syncthreads();
    int w = tid >> 5, lane = tid & 31;
    int n = blockIdx.x * 8 + w;
    if (n >= N) return;
    float v0 = emb[n*EE + lane];
    float v1 = emb[n*EE + 32 + lane];
    float s = v0*v0 + v1*v1;
    #pragma unroll
    for (int off = 16; off; off >>= 1) s += __shfl_xor_sync(0xffffffffu, s, off);
    float inv = 1.0f / fmaxf(sqrtf(s), 1e-12f);
    float h0 = v0 * inv, h1 = v1 * inv;
    items_out[n*EE + lane]      = h0;
    items_out[n*EE + 32 + lane] = h1;
    float d[KP];
    #pragma unroll
    for (int k = 0; k < KP; k++) {
        float dk = h0 * ps[k*EE + lane] + h1 * ps[k*EE + 32 + lane];
        #pragma unroll
        for (int off = 16; off; off >>= 1) dk += __shfl_xor_sync(0xffffffffu, dk, off);
        d[k] = dk;
    }
    if (lane == 0) {
        float m = fmaxf(fmaxf(d[0], d[1]), fmaxf(d[2], d[3]));
        float e0 = __expf(d[0]-m), e1 = __expf(d[1]-m), e2 = __expf(d[2]-m), e3 = __expf(d[3]-m);
        float is = 1.0f / (e0+e1+e2+e3);
        float c0 = e0*is, c1 = e1*is, c2 = e2*is, c3 = e3*is;
        *(float4*)&cates_out[n*KP] = make_float4(c0, c1, c2, c3);
        catesT_out[0*N + n] = c0;
        catesT_out[1*N + n] = c1;
        catesT_out[2*N + n] = c2;
        catesT_out[3*N + n] = c3;
    }
}

// ---------------- k2: rnorm partials ----------------
__global__ void __launch_bounds__(256) rnormp_k(
        const float* __restrict__ x, const float* __restrict__ cates,
        float* __restrict__ rnp, int N)
{
    __shared__ float red[8][KP];
    int b = blockIdx.x, chunk = blockIdx.y, tid = threadIdx.x;
    int n0 = chunk * (N >> 3), n1 = n0 + (N >> 3);
    float s0=0.f, s1=0.f, s2=0.f, s3=0.f;
    const float* xr = x + (size_t)b * N;
    for (int n = n0 + tid; n < n1; n += 256) {
        float xv = xr[n];
        float4 c = *(const float4*)&cates[n*KP];
        float t0 = xv*c.x, t1 = xv*c.y, t2 = xv*c.z, t3 = xv*c.w;
        s0 += t0*t0; s1 += t1*t1; s2 += t2*t2; s3 += t3*t3;
    }
    #pragma unroll
    for (int off = 16; off; off >>= 1) {
        s0 += __shfl_xor_sync(0xffffffffu, s0, off);
        s1 += __shfl_xor_sync(0xffffffffu, s1, off);
        s2 += __shfl_xor_sync(0xffffffffu, s2, off);
        s3 += __shfl_xor_sync(0xffffffffu, s3, off);
    }
    int w = tid >> 5;
    if ((tid & 31) == 0) { red[w][0]=s0; red[w][1]=s1; red[w][2]=s2; red[w][3]=s3; }
    __syncthreads();
    if (tid < KP) {
        float t = 0.f;
        #pragma unroll
        for (int i = 0; i < 8; i++) t += red[i][tid];
        rnp[(tid*BB + b)*8 + chunk] = t;
    }
}

// ---------------- FP16 MMA GEMM (templated A-mode), B fp16 via cp.async --------
// AMODE 0: A fp32 rows, cvt*ascale in producer; optional fp16 write-through to aout
// AMODE 1: A = x[m][n]*ctT[bx][n] on the fly
template<int AMODE>
__global__ void __launch_bounds__(256) mma_gemm_t(
        const float* __restrict__ A, const float* __restrict__ ctT,
        const __half* __restrict__ B16,
        float* __restrict__ part, __half* __restrict__ aout,
        int Mrows, int Ktot, int Ksplit, float ascale, float inv_ab)
{
    extern __shared__ __half hsm[];
    __half* Asm = hsm;
    int tid = threadIdx.x;
    int lane = tid & 31, w = tid >> 5;
    int wm = w & 3, wn = w >> 2;
    int lr = lane >> 2, lc = lane & 3;
    int m0 = blockIdx.x * 128;
    int kc0 = blockIdx.z * Ksplit;
    int niter = Ksplit / BLKK;
    const float* ctb = (AMODE == 1) ? (ctT + (size_t)blockIdx.x * Ktot) : (const float*)0;

    uint32_t as_base = (uint32_t)__cvta_generic_to_shared(Asm);
    uint32_t bs_base = as_base + 2*BUF_BYTES;
    int sel = lane >> 3, lr8 = lane & 7;
    uint32_t a_off = (uint32_t)(((wm*32 + (sel&1)*8 + lr8)*LDH + (sel>>1)*8) * 2);
    uint32_t b_off = (uint32_t)(((wn*64 + (sel>>1)*8 + lr8)*LDH + (sel&1)*8) * 2);

    float acc[2][8][4];
    #pragma unroll
    for (int mt = 0; mt < 2; mt++)
        #pragma unroll
        for (int nt = 0; nt < 8; nt++)
            #pragma unroll
            for (int i = 0; i < 4; i++) acc[mt][nt][i] = 0.f;

    float4 ra[4];
    int co = tid >> 1, ck0 = (tid & 1) * 16;

    auto ldA = [&](int kc) {
        #pragma unroll
        for (int i = 0; i < 4; i++) {
            int lin = tid + i*256;
            int mm = lin >> 3, kk = (lin & 7) * 4;
            if (AMODE == 0) {
                ra[i] = *(const float4*)(A + (size_t)(m0 + mm) * Ktot + kc + kk);
            } else {
                float4 v = *(const float4*)(A + (size_t)mm * Ktot + kc + kk);
                float4 c = *(const float4*)(ctb + kc + kk);
                v.x *= c.x; v.y *= c.y; v.z *= c.z; v.w *= c.w;
                ra[i] = v;
            }
        }
    };
    auto stA = [&](int buf, int kc) {
        __half* base = Asm + buf*BUFH;
        #pragma unroll
        for (int i = 0; i < 4; i++) {
            int lin = tid + i*256;
            int mm = lin >> 3, kk = (lin & 7) * 4;
            uint2 u;
            u.x = pack_h2(ra[i].x*ascale, ra[i].y*ascale);
            u.y = pack_h2(ra[i].z*ascale, ra[i].w*ascale);
            *(uint2*)(base + mm*LDH + kk) = u;
            if (AMODE == 0 && aout)
                *(uint2*)(aout + (size_t)(m0 + mm) * Ktot + kc + kk) = u;
        }
    };
    auto issueB = [&](int buf, int kc) {
        uint32_t dst = bs_base + buf*BUF_BYTES + (uint32_t)(co*LDH + ck0)*2;
        const __half* src = B16 + (size_t)co * Ktot + kc + ck0;
        CP16(dst,      src);
        CP16(dst + 16, src + 8);
    };
    auto compute = [&](int buf) {
        uint32_t abase = as_base + buf*BUF_BYTES + a_off;
        uint32_t bbase = bs_base + buf*BUF_BYTES + b_off;
        #pragma unroll
        for (int ks = 0; ks < 2; ks++) {
            int kb = ks * 16 * 2;
            uint32_t afr[2][4];
            #pragma unroll
            for (int mt = 0; mt < 2; mt++)
                ldsm4(afr[mt][0], afr[mt][1], afr[mt][2], afr[mt][3],
                      abase + mt*(16*LDH*2) + kb);
            #pragma unroll
            for (int npp = 0; npp < 4; npp++) {
                uint32_t b0, b1, b2, b3;
                ldsm4(b0, b1, b2, b3, bbase + npp*(16*LDH*2) + kb);
                mma_f16(acc[0][2*npp  ], afr[0], b0, b1);
                mma_f16(acc[1][2*npp  ], afr[1], b0, b1);
                mma_f16(acc[0][2*npp+1], afr[0], b2, b3);
                mma_f16(acc[1][2*npp+1], afr[1], b2, b3);
            }
        }
    };

    issueB(0, kc0);
    CP_COMMIT();
    ldA(kc0); stA(0, kc0);
    CP_WAIT0();
    __syncthreads();

    for (int it = 0; it < niter; it++) {
        int cur = it & 1;
        int kcn = kc0 + (it+1)*BLKK;
        if (it + 1 < niter) {
            issueB(1-cur, kcn);
            CP_COMMIT();
            ldA(kcn);
        }
        compute(cur);
        if (it + 1 < niter) {
            stA(1-cur, kcn);
            CP_WAIT0();
        }
        __syncthreads();
    }

    #pragma unroll
    for (int mt = 0; mt < 2; mt++)
        #pragma unroll
        for (int nt = 0; nt < 8; nt++) {
            int row = m0 + wm*32 + mt*16 + lr;
            int col = wn*64 + nt*8 + lc*2;
            float* p = part + ((size_t)blockIdx.z * Mrows + row) * TWOE + col;
            *(float2*)p            = make_float2(acc[mt][nt][0]*inv_ab, acc[mt][nt][1]*inv_ab);
            *(float2*)(p + 8*TWOE) = make_float2(acc[mt][nt][2]*inv_ab, acc[mt][nt][3]*inv_ab);
        }
}

// ---------------- FP16 GEMM, A and B fp16 via cp.async, 4-stage pipeline -------
__global__ void __launch_bounds__(256) mma_gemm_a16(
        const __half* __restrict__ A16, const __half* __restrict__ B16,
        float* __restrict__ part, int Mrows, int Ktot, int Ksplit, float inv_ab)
{
    extern __shared__ __half hsm[];
    int tid = threadIdx.x;
    int lane = tid & 31, w = tid >> 5;
    int wm = w & 3, wn = w >> 2;
    int lr = lane >> 2, lc = lane & 3;
    int m0 = blockIdx.x * 128;
    int kc0 = blockIdx.z * Ksplit;
    int niter = Ksplit / BLKK;

    uint32_t as_base = (uint32_t)__cvta_generic_to_shared(hsm);
    uint32_t bs_base = as_base + 4*BUF_BYTES;
    int sel = lane >> 3, lr8 = lane & 7;
    uint32_t a_off = (uint32_t)(((wm*32 + (sel&1)*8 + lr8)*LDH + (sel>>1)*8) * 2);
    uint32_t b_off = (uint32_t)(((wn*64 + (sel>>1)*8 + lr8)*LDH + (sel&1)*8) * 2);

    float acc[2][8][4];
    #pragma unroll
    for (int mt = 0; mt < 2; mt++)
        #pragma unroll
        for (int nt = 0; nt < 8; nt++)
            #pragma unroll
            for (int i = 0; i < 4; i++) acc[mt][nt][i] = 0.f;

    int co = tid >> 1, ck0 = (tid & 1) * 16;

    auto issueAB = [&](int s, int kc) {
        uint32_t adst = as_base + s*BUF_BYTES + (uint32_t)(co*LDH + ck0)*2;
        const __half* asrc = A16 + (size_t)(m0 + co) * Ktot + kc + ck0;
        CP16(adst,      asrc);
        CP16(adst + 16, asrc + 8);
        uint32_t bdst = bs_base + s*BUF_BYTES + (uint32_t)(co*LDH + ck0)*2;
        const __half* bsrc = B16 + (size_t)co * Ktot + kc + ck0;
        CP16(bdst,      bsrc);
        CP16(bdst + 16, bsrc + 8);
    };
    auto compute = [&](int s) {
        uint32_t abase = as_base + s*BUF_BYTES + a_off;
        uint32_t bbase = bs_base + s*BUF_BYTES + b_off;
        #pragma unroll
        for (int ks = 0; ks < 2; ks++) {
            int kb = ks * 16 * 2;
            uint32_t afr[2][4];
            #pragma unroll
            for (int mt = 0; mt < 2; mt++)
                ldsm4(afr[mt][0], afr[mt][1], afr[mt][2], afr[mt][3],
                      abase + mt*(16*LDH*2) + kb);
            #pragma unroll
            for (int npp = 0; npp < 4; npp++) {
                uint32_t b0, b1, b2, b3;
                ldsm4(b0, b1, b2, b3, bbase + npp*(16*LDH*2) + kb);
                mma_f16(acc[0][2*npp  ], afr[0], b0, b1);
                mma_f16(acc[1][2*npp  ], afr[1], b0, b1);
                mma_f16(acc[0][2*npp+1], afr[0], b2, b3);
                mma_f16(acc[1][2*npp+1], afr[1], b2, b3);
            }
        }
    };

    // prologue: 3 tiles in flight
    issueAB(0, kc0);           CP_COMMIT();
    issueAB(1, kc0 + BLKK);    CP_COMMIT();
    issueAB(2, kc0 + 2*BLKK);  CP_COMMIT();
    CP_WAIT2();                // tile 0 landed
    __syncthreads();

    int cur = 0;
    for (int it = 0; it < niter; it++) {
        compute(cur);
        if (it + 3 < niter) {
            issueAB((cur + 3) & 3, kc0 + (it+3)*BLKK);
            CP_COMMIT();
            CP_WAIT2();                          // tile it+1 landed
        } else if (it + 2 < niter) {
            CP_WAIT1();
        } else if (it + 1 < niter) {
            CP_WAIT0();
        }
        __syncthreads();
        cur = (cur + 1) & 3;
    }

    #pragma unroll
    for (int mt = 0; mt < 2; mt++)
        #pragma unroll
        for (int nt = 0; nt < 8; nt++) {
            int row = m0 + wm*32 + mt*16 + lr;
            int col = wn*64 + nt*8 + lc*2;
            float* p = part + ((size_t)blockIdx.z * Mrows + row) * TWOE + col;
            *(float2*)p            = make_float2(acc[mt][nt][0]*inv_ab, acc[mt][nt][1]*inv_ab);
            *(float2*)(p + 8*TWOE) = make_float2(acc[mt][nt][2]*inv_ab, acc[mt][nt][3]*inv_ab);
        }
}

// ---------------- reduce split-K partials + transpose, emit scaled fp16 ----------
__global__ void __launch_bounds__(256) reduceT_k(
        const float* __restrict__ part, const float* __restrict__ W,
        __half* __restrict__ outT, int combine, float oscale)
{
    __shared__ float t[64][65];
    int n0 = blockIdx.x * 64, o0 = blockIdx.y * 64;
    int c0 = threadIdx.x & 63, r4 = threadIdx.x >> 6;
    #pragma unroll
    for (int p = 0; p < 16; p++) {
        int nl = p*4 + r4;
        float s = 0.f;
        #pragma unroll
        for (int z = 0; z < ASPLIT; z++)
            s += part[((size_t)z*NI + n0 + nl)*TWOE + o0 + c0];
        t[nl][c0] = s;
    }
    __syncthreads();
    #pragma unroll
    for (int p = 0; p < 16; p++) {
        int ol = p*4 + r4;
        float v = t[c0][ol];
        if (combine) v = 0.5f*(v + W[(size_t)(o0+ol)*NI + n0 + c0]);
        outT[(size_t)(o0+ol)*NI + n0 + c0] = __float2half_rn(v * oscale);
    }
}

// ---------------- finalize h -> mu / logvar ----------------
__global__ void __launch_bounds__(128) hfinal_k(
        const float* __restrict__ part, int nchunks,
        const float* __restrict__ rnp, const float* __restrict__ bias,
        float* __restrict__ out_mu, float* __restrict__ out_lv)
{
    __shared__ float sq[64];
    __shared__ float sinv, s_rn;
    int kb = blockIdx.x, o = threadIdx.x;
    if (o == 0) {
        float t = 0.f;
        #pragma unroll
        for (int c = 0; c < 8; c++) t += rnp[kb*8 + c];
        s_rn = 1.0f / fmaxf(sqrtf(t), 1e-12f);
    }
    float s = 0.f;
    for (int c = 0; c < nchunks; c++) s += part[(size_t)c*512*TWOE + (size_t)kb*TWOE + o];
    __syncthreads();
    float h = s * s_rn + bias[o];
    if (o < 64) sq[o] = h*h;
    __syncthreads();
    if (o == 0) {
        float t = 0.f;
        #pragma unroll
        for (int i = 0; i < 64; i++) t += sq[i];
        sinv = 1.0f / fmaxf(sqrtf(t), 1e-12f);
    }
    __syncthreads();
    if (o < 64) out_mu[(size_t)kb*EE + o] = h * sinv;
    else        out_lv[(size_t)kb*EE + (o-64)] = -h;
}

// ---------------- decoder (FMA-pipe exp/log polynomials) ----------------
__global__ void __launch_bounds__(256) decoder_k(
        const float* __restrict__ items, const float* __restrict__ cates,
        const float* __restrict__ mu, float* __restrict__ out, int N)
{
    __shared__ float itemsT[64][68];
    __shared__ float mu_s[16][64][4];
    __shared__ float cs[64][4];
    int tid = threadIdx.x;
    int tx = tid & 15, ty = tid >> 4;
    int n0 = blockIdx.x * 64;
    int bt = blockIdx.y * 16;
    #pragma unroll
    for (int i = 0; i < 16; i++) {
        int idx = tid + i*256;
        int n = idx >> 6, e = idx & 63;
        itemsT[e][n] = items[(size_t)(n0+n)*EE + e];
    }
    #pragma unroll
    for (int i = 0; i < 16; i++) {
        int idx = tid + i*256;
        int kb = idx >> 6, e = idx & 63;
        int k = kb >> 4, b = kb & 15;
        mu_s[b][e][k] = mu[(size_t)(k*BB + bt + b)*EE + e];
    }
    {
        int n = tid >> 2, kk = tid & 3;
        cs[n][kk] = cates[(size_t)(n0+n)*KP + kk];
    }
    __syncthreads();

    float acc[4][KP];
    #pragma unroll
    for (int i = 0; i < 4; i++)
        #pragma unroll
        for (int k = 0; k < KP; k++) acc[i][k] = 0.f;

    #pragma unroll 4
    for (int e = 0; e < 64; e++) {
        float4 a = *(const float4*)&itemsT[e][tx*4];
        float4 mm = *(const float4*)&mu_s[ty][e][0];
        float aw[4] = {a.x, a.y, a.z, a.w};
        #pragma unroll
        for (int i = 0; i < 4; i++) {
            acc[i][0] += aw[i]*mm.x; acc[i][1] += aw[i]*mm.y;
            acc[i][2] += aw[i]*mm.z; acc[i][3] += aw[i]*mm.w;
        }
    }
    int b = bt + ty;
    #pragma unroll
    for (int i = 0; i < 4; i++) {
        int nl = tx*4 + i;
        float4 c = *(const float4*)&cs[nl][0];
        float p = exp_t9(acc[i][0])*c.x + exp_t9(acc[i][1])*c.y
                + exp_t9(acc[i][2])*c.z + exp_t9(acc[i][3])*c.w;
        out[(size_t)b*N + n0 + nl] = log_poly(p);
    }
}

// ---------------- launch ----------------
extern "C" void kernel_launch(void* const* d_in, const int* in_sizes, int n_in,
                              void* d_out, int out_size)
{
    const float* x_cf    = (const float*)d_in[0];
    const float* x_tx    = (const float*)d_in[1];
    const float* adj     = (const float*)d_in[2];
    const float* cf_emb  = (const float*)d_in[3];
    const float* cf_prot = (const float*)d_in[4];
    const float* cf_W    = (const float*)d_in[5];
    const float* cf_b    = (const float*)d_in[6];
    const float* tx_emb  = (const float*)d_in[7];
    const float* tx_prot = (const float*)d_in[8];
    const float* tx_W    = (const float*)d_in[9];
    const float* tx_b    = (const float*)d_in[10];
    float* out = (float*)d_out;

    float *p_protos_cf, *p_protos_tx, *p_items_cf, *p_items_tx;
    float *p_cates_cf, *p_cates_tx, *p_ctT_cf, *p_ctT_tx, *p_rnp_cf, *p_rnp_tx;
    float *p_big, *p_part_cf, *p_part_tx;
    __half *p_adj16, *p_W16cf, *p_W16tx, *p_P1T16, *p_MT16, *p_Y16cf;
    cudaGetSymbolAddress((void**)&p_protos_cf, g_protos_cf);
    cudaGetSymbolAddress((void**)&p_protos_tx, g_protos_tx);
    cudaGetSymbolAddress((void**)&p_items_cf,  g_items_cf);
    cudaGetSymbolAddress((void**)&p_items_tx,  g_items_tx);
    cudaGetSymbolAddress((void**)&p_cates_cf,  g_cates_cf);
    cudaGetSymbolAddress((void**)&p_cates_tx,  g_cates_tx);
    cudaGetSymbolAddress((void**)&p_ctT_cf,    g_ctT_cf);
    cudaGetSymbolAddress((void**)&p_ctT_tx,    g_ctT_tx);
    cudaGetSymbolAddress((void**)&p_rnp_cf,    g_rnp_cf);
    cudaGetSymbolAddress((void**)&p_rnp_tx,    g_rnp_tx);
    cudaGetSymbolAddress((void**)&p_adj16,     g_adj16);
    cudaGetSymbolAddress((void**)&p_W16cf,     g_W16cf);
    cudaGetSymbolAddress((void**)&p_W16tx,     g_W16tx);
    cudaGetSymbolAddress((void**)&p_P1T16,     g_P1T16);
    cudaGetSymbolAddress((void**)&p_MT16,      g_MT16);
    cudaGetSymbolAddress((void**)&p_Y16cf,     g_Y16cf);
    cudaGetSymbolAddress((void**)&p_big,       g_bigpart);
    cudaGetSymbolAddress((void**)&p_part_cf,   g_part_cf);
    cudaGetSymbolAddress((void**)&p_part_tx,   g_part_tx);

    static cudaStream_t s_tx = nullptr, s_pre = nullptr;
    static cudaEvent_t ev_fork = nullptr, ev_proto = nullptr, ev_tx = nullptr, ev_pre = nullptr;
    if (!s_tx) {
        cudaStreamCreateWithFlags(&s_tx,  cudaStreamNonBlocking);
        cudaStreamCreateWithFlags(&s_pre, cudaStreamNonBlocking);
        cudaEventCreateWithFlags(&ev_fork,  cudaEventDisableTiming);
        cudaEventCreateWithFlags(&ev_proto, cudaEventDisableTiming);
        cudaEventCreateWithFlags(&ev_tx,    cudaEventDisableTiming);
        cudaEventCreateWithFlags(&ev_pre,   cudaEventDisableTiming);
        cudaFuncSetAttribute(mma_gemm_a16,
            cudaFuncAttributeMaxDynamicSharedMemorySize, SMEM_A16);
    }

    // ---- fork immediately; main stream carries only the adjacency chain ----
    cudaEventRecord(ev_fork, 0);
    cudaStreamWaitEvent(s_pre, ev_fork, 0);
    cudaStreamWaitEvent(s_tx,  ev_fork, 0);

    // ---- s_pre: prototypes + cf prep + Y16 build ----
    proto_norm_k<<<1, 256, 0, s_pre>>>(cf_prot, tx_prot);
    cudaEventRecord(ev_proto, s_pre);
    items_cates_k<<<NI/8, 256, 0, s_pre>>>(cf_emb, p_protos_cf, p_items_cf, p_cates_cf, p_ctT_cf, NI);
    rnormp_k<<<dim3(BB, 8), 256, 0, s_pre>>>(x_cf, p_cates_cf, p_rnp_cf, NI);
    buildY_k<<<dim3(512, NI/1024), 256, 0, s_pre>>>(x_cf, p_ctT_cf, p_Y16cf, NI, 16.0f);
    cudaEventRecord(ev_pre, s_pre);

    // ---- s_tx: text branch ----
    convW_k<<<TWOE*NW/4/256, 256, 0, s_tx>>>((const float4*)tx_W, (uint2*)p_W16tx, 64.0f);
    cudaStreamWaitEvent(s_tx, ev_proto, 0);
    items_cates_k<<<NW/8, 256, 0, s_tx>>>(tx_emb, p_protos_tx, p_items_tx, p_cates_tx, p_ctT_tx, NW);
    rnormp_k<<<dim3(BB, 8), 256, 0, s_tx>>>(x_tx, p_cates_tx, p_rnp_tx, NW);
    mma_gemm_t<1><<<dim3(4, 1, HSPLIT), 256, SMEM_GEMM, s_tx>>>(
        x_tx, p_ctT_tx, p_W16tx, p_part_tx, nullptr,
        512, NW, NW/HSPLIT, 16.0f, 1.0f/1024.0f);
    hfinal_k<<<KP*BB, 128, 0, s_tx>>>(p_part_tx, HSPLIT, p_rnp_tx, tx_b,
                                      out + OUT_TXMU, out + OUT_TXLV);
    decoder_k<<<dim3(NW/64, BB/16), 256, 0, s_tx>>>(p_items_tx, p_cates_tx,
                                                    out + OUT_TXMU, out + OUT_TEXT, NW);
    cudaEventRecord(ev_tx, s_tx);

    // ---- main stream: adjacency chain ----
    convW_k<<<TWOE*NI/4/256, 256>>>((const float4*)cf_W, (uint2*)p_W16cf, 64.0f);
    // P1 = adj @ cf_W^T (A fp32, write adj16) -> P1T16
    mma_gemm_t<0><<<dim3(NI/128, 1, ASPLIT), 256, SMEM_GEMM>>>(
        adj, nullptr, p_W16cf, p_big, p_adj16,
        NI, NI, NI/ASPLIT, 4096.0f, 1.0f/(4096.0f*64.0f));
    reduceT_k<<<dim3(NI/64, 2), 256>>>(p_big, nullptr, p_P1T16, 0, 4096.0f);
    // P2 = adj16 @ P1T16 (both fp16, 4-stage cp.async) -> MT16
    mma_gemm_a16<<<dim3(NI/128, 1, ASPLIT), 256, SMEM_A16>>>(
        p_adj16, p_P1T16, p_big, NI, NI, NI/ASPLIT, 1.0f/(4096.0f*4096.0f));
    reduceT_k<<<dim3(NI/64, 2), 256>>>(p_big, cf_W, p_MT16, 1, 64.0f);

    // hpart_cf: pure fp16 cp.async GEMM on precomputed Y16 (4-stage)
    cudaStreamWaitEvent(0, ev_pre, 0);
    mma_gemm_a16<<<dim3(4, 1, HSPLIT), 256, SMEM_A16>>>(
        p_Y16cf, p_MT16, p_part_cf, 512, NI, NI/HSPLIT, 1.0f/1024.0f);
    hfinal_k<<<KP*BB, 128>>>(p_part_cf, HSPLIT, p_rnp_cf, cf_b,
                             out + OUT_CFMU, out + OUT_CFLV);
    decoder_k<<<dim3(NI/64, BB/16), 256>>>(p_items_cf, p_cates_cf,
                                           out + OUT_CFMU, out + OUT_RATING, NI);

    cudaStreamWaitEvent(0, ev_tx, 0);
}